// round 13
// baseline (speedup 1.0000x reference)
#include <cuda_runtime.h>
#include <cuda_bf16.h>
#include <cuda_fp16.h>
#include <math.h>
#include <stdint.h>

// ---------------- problem dims ----------------
#define TB 2048
#define SEQ 1024
#define BATCH 2
#define DIM 768
#define NH 12
#define HD 64
#define DLAT 192
#define DFF 3072
#define NE 8
#define NV 32000
#define NLAYER 2

#define FLAG_ACC 1
#define FLAG_GELU 2

typedef __nv_bfloat16 bf16;

// ---------------- fp32 scratch ----------------
__device__ float g_x[TB * DIM];
__device__ float g_h[TB * DIM];
__device__ float g_q[TB * DIM];
__device__ float g_k[TB * DIM];
__device__ float g_v[TB * DIM];
__device__ float g_yff[2 * TB * DIM];
__device__ float g_tw[TB * 2];
__device__ int   g_te[TB * 2];
__device__ int   g_counts[NE];
__device__ int   g_offsets[NE];
__device__ int   g_rowtok[2 * TB];
__device__ float g_roww[2 * TB];
__device__ int   g_perm[2 * TB];

// ---------------- bf16 (or fp16, final layer) hi/lo activations ----------------
__device__ bf16 g_hh[TB * DIM],  g_hl[TB * DIM];
__device__ bf16 g_lath[TB * DLAT], g_latl[TB * DLAT];
__device__ bf16 g_aoh[TB * DIM], g_aol[TB * DIM];
__device__ bf16 g_hffh[2 * TB * DFF], g_hffl[2 * TB * DFF];

// ---------------- bf16 hi/lo weights (+ fp16 Wout) ----------------
__device__ bf16 g_wqh[NLAYER * DIM * DIM],  g_wql[NLAYER * DIM * DIM];
__device__ bf16 g_wkvh[NLAYER * DIM * DLAT], g_wkvl[NLAYER * DIM * DLAT];
__device__ bf16 g_wkh[NLAYER * DLAT * DIM], g_wkl[NLAYER * DLAT * DIM];
__device__ bf16 g_wvh[NLAYER * DLAT * DIM], g_wvl[NLAYER * DLAT * DIM];
__device__ bf16 g_woh[NLAYER * DIM * DIM],  g_wol[NLAYER * DIM * DIM];
__device__ bf16 g_w1h[NLAYER * NE * DIM * DFF], g_w1l[NLAYER * NE * DIM * DFF];
__device__ bf16 g_w2h[NLAYER * NE * DFF * DIM], g_w2l[NLAYER * NE * DFF * DIM];
__device__ __half g_wouth[DIM * NV];

// ---------------- helpers ----------------
__device__ __forceinline__ uint32_t smem_u32(const void* p) {
    uint32_t a;
    asm("{ .reg .u64 t; cvta.to.shared.u64 t, %1; cvt.u32.u64 %0, t; }" : "=r"(a) : "l"(p));
    return a;
}
__device__ __forceinline__ uint32_t pack_bf2(float a, float b) {
    __nv_bfloat162 h = __floats2bfloat162_rn(a, b);
    return *(uint32_t*)&h;
}
__device__ __forceinline__ void split_bf(float x, float& hi, float& lo) {
    bf16 h = __float2bfloat16_rn(x);
    hi = __bfloat162float(h);
    lo = x - hi;
}
__device__ __forceinline__ float gelu_f(float x) {
    const float k0 = 0.7978845608028654f;
    float x3 = x * x * x;
    return 0.5f * x * (1.0f + tanhf(k0 * (x + 0.044715f * x3)));
}
__device__ __forceinline__ void mma16(float d[4], const uint32_t a[4], const uint32_t b[2]) {
    asm volatile(
        "mma.sync.aligned.m16n8k16.row.col.f32.bf16.bf16.f32 "
        "{%0,%1,%2,%3},{%4,%5,%6,%7},{%8,%9},{%0,%1,%2,%3};"
        : "+f"(d[0]), "+f"(d[1]), "+f"(d[2]), "+f"(d[3])
        : "r"(a[0]), "r"(a[1]), "r"(a[2]), "r"(a[3]),
          "r"(b[0]), "r"(b[1]));
}
__device__ __forceinline__ void mma16h(float d[4], const uint32_t a[4], const uint32_t b[2]) {
    asm volatile(
        "mma.sync.aligned.m16n8k16.row.col.f32.f16.f16.f32 "
        "{%0,%1,%2,%3},{%4,%5,%6,%7},{%8,%9},{%0,%1,%2,%3};"
        : "+f"(d[0]), "+f"(d[1]), "+f"(d[2]), "+f"(d[3])
        : "r"(a[0]), "r"(a[1]), "r"(a[2]), "r"(a[3]),
          "r"(b[0]), "r"(b[1]));
}
__device__ __forceinline__ void ldsm4(uint32_t r[4], uint32_t addr) {
    asm volatile("ldmatrix.sync.aligned.m8n8.x4.shared.b16 {%0,%1,%2,%3}, [%4];"
                 : "=r"(r[0]), "=r"(r[1]), "=r"(r[2]), "=r"(r[3]) : "r"(addr));
}
__device__ __forceinline__ void ldsm4t(uint32_t& r0, uint32_t& r1, uint32_t& r2,
                                       uint32_t& r3, uint32_t addr) {
    asm volatile("ldmatrix.sync.aligned.m8n8.x4.trans.shared.b16 {%0,%1,%2,%3}, [%4];"
                 : "=r"(r0), "=r"(r1), "=r"(r2), "=r"(r3) : "r"(addr));
}
__device__ __forceinline__ void cpa16(uint32_t dst, const void* src, int sz) {
    asm volatile("cp.async.cg.shared.global [%0], [%1], 16, %2;"
                 :: "r"(dst), "l"(src), "r"(sz) : "memory");
}
__device__ __forceinline__ void cpa16f(uint32_t dst, const void* src) {
    asm volatile("cp.async.cg.shared.global [%0], [%1], 16;"
                 :: "r"(dst), "l"(src) : "memory");
}
#define CP_COMMIT() asm volatile("cp.async.commit_group;" ::: "memory")
#define CP_WAIT1()  asm volatile("cp.async.wait_group 1;" ::: "memory")

// ---------------- weight fp32 -> bf16 hi/lo conversion ----------------
__device__ __forceinline__ void wconv_body(const float* __restrict__ s,
                                           bf16* __restrict__ h, bf16* __restrict__ l,
                                           int i, int n4) {
    if (i >= n4) return;
    float4 v = ((const float4*)s)[i];
    float h0, l0, h1, l1, h2, l2, h3, l3;
    split_bf(v.x, h0, l0); split_bf(v.y, h1, l1);
    split_bf(v.z, h2, l2); split_bf(v.w, h3, l3);
    ((uint2*)h)[i] = make_uint2(pack_bf2(h0, h1), pack_bf2(h2, h3));
    ((uint2*)l)[i] = make_uint2(pack_bf2(l0, l1), pack_bf2(l2, l3));
}

__global__ void wconv_kernel(const float* __restrict__ s, bf16* __restrict__ h,
                             bf16* __restrict__ l, int n4) {
    wconv_body(s, h, l, blockIdx.x * blockDim.x + threadIdx.x, n4);
}

__global__ void wconv3_kernel(const float* __restrict__ s0, bf16* __restrict__ h0, bf16* __restrict__ l0,
                              const float* __restrict__ s1, bf16* __restrict__ h1, bf16* __restrict__ l1,
                              const float* __restrict__ s2, bf16* __restrict__ h2, bf16* __restrict__ l2,
                              int n4) {
    const float* s; bf16 *h, *l;
    if (blockIdx.y == 0)      { s = s0; h = h0; l = l0; }
    else if (blockIdx.y == 1) { s = s1; h = h1; l = l1; }
    else                      { s = s2; h = h2; l = l2; }
    wconv_body(s, h, l, blockIdx.x * blockDim.x + threadIdx.x, n4);
}

// fp32 -> fp16 (hi only, for Wout)
__global__ void wconvh_kernel(const float* __restrict__ s, __half* __restrict__ h, int n4) {
    int i = blockIdx.x * blockDim.x + threadIdx.x;
    if (i >= n4) return;
    float4 v = ((const float4*)s)[i];
    __half2 p0 = __floats2half2_rn(v.x, v.y);
    __half2 p1 = __floats2half2_rn(v.z, v.w);
    ((uint2*)h)[i] = make_uint2(*(uint32_t*)&p0, *(uint32_t*)&p1);
}

// =====================================================================
//   bf16x3 mma.sync GEMM, cp.async 3-stage pipeline, ldmatrix(.trans)
// =====================================================================
#define A_ROW_B 80
#define B_ROW_B 144
#define AL_B 10240
#define BH_B 20480
#define BL_B 25088
#define STAGE_B 29696
#define NSTAGE 3
#define GSMEM (STAGE_B * NSTAGE)

__device__ __forceinline__ void gemm_tile(
    const bf16* __restrict__ Ah, const bf16* __restrict__ Al,
    const int* __restrict__ Aidx,
    const bf16* __restrict__ Bh, const bf16* __restrict__ Bl,
    const float* __restrict__ bias,
    float* __restrict__ C, bf16* __restrict__ Chi, bf16* __restrict__ Clo,
    int Mv, int N, int K, int m0, int n0, int flags)
{
    extern __shared__ uint32_t smu[];
    const uint32_t sb0 = smem_u32(smu);
    int tid = threadIdx.x, lane = tid & 31, warp = tid >> 5;
    int wm = (warp >> 1) * 32, wn = (warp & 1) * 32;

    int jA = tid & 3, rA = tid >> 2;
    int kB = tid >> 3, jB = tid & 7;
    int gmr0 = m0 + rA, gmr1 = m0 + rA + 64;
    int szA0 = gmr0 < Mv ? 16 : 0;
    int szA1 = gmr1 < Mv ? 16 : 0;
    int row0 = gmr0 < Mv ? (Aidx ? Aidx[gmr0] : gmr0) : 0;
    int row1 = gmr1 < Mv ? (Aidx ? Aidx[gmr1] : gmr1) : 0;
    const bf16* pAh0 = Ah + (size_t)row0 * K + jA * 8;
    const bf16* pAl0 = Al + (size_t)row0 * K + jA * 8;
    const bf16* pAh1 = Ah + (size_t)row1 * K + jA * 8;
    const bf16* pAl1 = Al + (size_t)row1 * K + jA * 8;
    const bf16* pBh = Bh + (size_t)kB * N + n0 + jB * 8;
    const bf16* pBl = Bl + (size_t)kB * N + n0 + jB * 8;
    uint32_t dA0 = rA * A_ROW_B + jA * 16;
    uint32_t dA1 = dA0 + 64 * A_ROW_B;
    uint32_t dB  = kB * B_ROW_B + jB * 16;

    const int nk = K / 32;

    auto load_stage = [&](int c) {
        if (c < nk) {
            uint32_t st = sb0 + (c % NSTAGE) * STAGE_B;
            int kc = c * 32;
            size_t bo = (size_t)kc * N;
            cpa16(st + dA0, pAh0 + kc, szA0);
            cpa16(st + dA1, pAh1 + kc, szA1);
            cpa16(st + AL_B + dA0, pAl0 + kc, szA0);
            cpa16(st + AL_B + dA1, pAl1 + kc, szA1);
            cpa16(st + BH_B + dB, pBh + bo, 16);
            cpa16(st + BL_B + dB, pBl + bo, 16);
        }
        CP_COMMIT();
    };

    float acc[2][4][4] = {};

    load_stage(0);
    load_stage(1);

    uint32_t aAddr = (uint32_t)((wm + (lane & 15)) * A_ROW_B + ((lane >> 4) << 4));
    uint32_t bAddr = (uint32_t)(BH_B + (lane & 15) * B_ROW_B
                                + (wn + ((lane >> 4) << 3)) * 2);

    for (int c = 0; c < nk; c++) {
        CP_WAIT1();
        __syncthreads();
        load_stage(c + 2);

        uint32_t st = sb0 + (c % NSTAGE) * STAGE_B;
#pragma unroll
        for (int ss = 0; ss < 2; ss++) {
            uint32_t ah[2][4], al[2][4], bh[4][2], bl[4][2];
#pragma unroll
            for (int mt = 0; mt < 2; mt++) {
                uint32_t ao = st + aAddr + mt * 16 * A_ROW_B + ss * 32;
                ldsm4(ah[mt], ao);
                ldsm4(al[mt], ao + AL_B);
            }
#pragma unroll
            for (int ntp = 0; ntp < 2; ntp++) {
                uint32_t bo = st + bAddr + ss * 16 * B_ROW_B + ntp * 32;
                ldsm4t(bh[2 * ntp][0], bh[2 * ntp][1],
                       bh[2 * ntp + 1][0], bh[2 * ntp + 1][1], bo);
                ldsm4t(bl[2 * ntp][0], bl[2 * ntp][1],
                       bl[2 * ntp + 1][0], bl[2 * ntp + 1][1], bo + (BL_B - BH_B));
            }
#pragma unroll
            for (int mt = 0; mt < 2; mt++)
#pragma unroll
                for (int nt = 0; nt < 4; nt++) mma16(acc[mt][nt], ah[mt], bh[nt]);
#pragma unroll
            for (int mt = 0; mt < 2; mt++)
#pragma unroll
                for (int nt = 0; nt < 4; nt++) mma16(acc[mt][nt], ah[mt], bl[nt]);
#pragma unroll
            for (int mt = 0; mt < 2; mt++)
#pragma unroll
                for (int nt = 0; nt < 4; nt++) mma16(acc[mt][nt], al[mt], bh[nt]);
        }
    }

    int row = lane >> 2, cc = lane & 3;
#pragma unroll
    for (int mt = 0; mt < 2; mt++) {
#pragma unroll
        for (int h = 0; h < 2; h++) {
            int r = m0 + wm + mt * 16 + row + h * 8;
            if (r >= Mv) continue;
#pragma unroll
            for (int nt = 0; nt < 4; nt++) {
#pragma unroll
                for (int j = 0; j < 2; j++) {
                    int cn = n0 + wn + nt * 8 + cc * 2 + j;
                    float val = acc[mt][nt][h * 2 + j];
                    if (bias) val += bias[cn];
                    if (flags & FLAG_GELU) val = gelu_f(val);
                    size_t ix = (size_t)r * N + cn;
                    if (flags & FLAG_ACC) C[ix] += val;
                    else if (C) C[ix] = val;
                    if (Chi) {
                        bf16 hv = __float2bfloat16_rn(val);
                        Chi[ix] = hv;
                        Clo[ix] = __float2bfloat16_rn(val - __bfloat162float(hv));
                    }
                }
            }
        }
    }
}

__global__ void __launch_bounds__(256, 2) qkv1_kernel(int l) {
    int bx = blockIdx.x;
    size_t wq = (size_t)l * DIM * DIM, wkv = (size_t)l * DIM * DLAT;
    if (bx < 12)
        gemm_tile(g_hh, g_hl, nullptr, g_wqh + wq, g_wql + wq, nullptr,
                  g_q, nullptr, nullptr, TB, DIM, DIM, blockIdx.y * 128, bx * 64, 0);
    else
        gemm_tile(g_hh, g_hl, nullptr, g_wkvh + wkv, g_wkvl + wkv, nullptr,
                  nullptr, g_lath, g_latl, TB, DLAT, DIM,
                  blockIdx.y * 128, (bx - 12) * 64, 0);
}

__global__ void __launch_bounds__(256, 2) kv2_kernel(int l) {
    int bx = blockIdx.x;
    size_t w = (size_t)l * DLAT * DIM;
    if (bx < 12)
        gemm_tile(g_lath, g_latl, nullptr, g_wkh + w, g_wkl + w, nullptr,
                  g_k, nullptr, nullptr, TB, DIM, DLAT, blockIdx.y * 128, bx * 64, 0);
    else
        gemm_tile(g_lath, g_latl, nullptr, g_wvh + w, g_wvl + w, nullptr,
                  g_v, nullptr, nullptr, TB, DIM, DLAT,
                  blockIdx.y * 128, (bx - 12) * 64, 0);
}

__global__ void __launch_bounds__(256, 2) wo_kernel(int l) {
    size_t w = (size_t)l * DIM * DIM;
    gemm_tile(g_aoh, g_aol, nullptr, g_woh + w, g_wol + w, nullptr,
              g_x, nullptr, nullptr, TB, DIM, DIM,
              blockIdx.y * 128, blockIdx.x * 64, FLAG_ACC);
}

__global__ void __launch_bounds__(256, 2) moe1_kernel(const float* __restrict__ b1, int l) {
    int e = blockIdx.z;
    int cnt = g_counts[e];
    int m0 = blockIdx.y * 128;
    if (m0 >= cnt) return;
    int off = g_offsets[e];
    size_t w = ((size_t)l * NE + e) * DIM * DFF;
    gemm_tile(g_hh, g_hl, g_rowtok + off, g_w1h + w, g_w1l + w,
              b1 + ((size_t)l * NE + e) * DFF,
              nullptr, g_hffh + (size_t)off * DFF, g_hffl + (size_t)off * DFF,
              cnt, DFF, DIM, m0, blockIdx.x * 64, FLAG_GELU);
}

__global__ void __launch_bounds__(256, 2) moe2_kernel(const float* __restrict__ b2, int l) {
    int e = blockIdx.z;
    int cnt = g_counts[e];
    int m0 = blockIdx.y * 128;
    if (m0 >= cnt) return;
    int off = g_offsets[e];
    size_t w = ((size_t)l * NE + e) * DFF * DIM;
    gemm_tile(g_hffh + (size_t)off * DFF, g_hffl + (size_t)off * DFF, nullptr,
              g_w2h + w, g_w2l + w, b2 + ((size_t)l * NE + e) * DIM,
              g_yff + (size_t)off * DIM, nullptr, nullptr,
              cnt, DIM, DFF, m0, blockIdx.x * 64, 0);
}

// =====================================================================
//  LM head: fp16 2-pass GEMM (A = lnf hi/lo fp16, B = Wout fp16)
//  D = (Ah + Al) @ Bh.  Stage: Ah 10240B | Al 10240B | Bh 4608B.
// =====================================================================
#define F16_AL_B 10240
#define F16_BH_B 20480
#define F16_STAGE_B 25088
#define GSMEM16 (F16_STAGE_B * NSTAGE)

__global__ void __launch_bounds__(256, 2) lmhead_kernel(float* __restrict__ out) {
    const __half* Ah = (const __half*)g_hh;
    const __half* Al = (const __half*)g_hl;
    const __half* Bh = g_wouth;
    const int N = NV, K = DIM;
    int m0 = blockIdx.y * 128, n0 = blockIdx.x * 64;

    extern __shared__ uint32_t smu[];
    const uint32_t sb0 = smem_u32(smu);
    int tid = threadIdx.x, lane = tid & 31, warp = tid >> 5;
    int wm = (warp >> 1) * 32, wn = (warp & 1) * 32;

    int jA = tid & 3, rA = tid >> 2;
    int kB = tid >> 3, jB = tid & 7;
    const __half* pAh0 = Ah + (size_t)(m0 + rA) * K + jA * 8;
    const __half* pAl0 = Al + (size_t)(m0 + rA) * K + jA * 8;
    const __half* pAh1 = pAh0 + (size_t)64 * K;
    const __half* pAl1 = pAl0 + (size_t)64 * K;
    const __half* pBh = Bh + (size_t)kB * N + n0 + jB * 8;
    uint32_t dA0 = rA * A_ROW_B + jA * 16;
    uint32_t dA1 = dA0 + 64 * A_ROW_B;
    uint32_t dB  = kB * B_ROW_B + jB * 16;

    const int nk = K / 32;

    auto load_stage = [&](int c) {
        if (c < nk) {
            uint32_t st = sb0 + (c % NSTAGE) * F16_STAGE_B;
            int kc = c * 32;
            cpa16f(st + dA0, pAh0 + kc);
            cpa16f(st + dA1, pAh1 + kc);
            cpa16f(st + F16_AL_B + dA0, pAl0 + kc);
            cpa16f(st + F16_AL_B + dA1, pAl1 + kc);
            cpa16f(st + F16_BH_B + dB, pBh + (size_t)kc * N);
        }
        CP_COMMIT();
    };

    float acc[2][4][4] = {};

    load_stage(0);
    load_stage(1);

    uint32_t aAddr = (uint32_t)((wm + (lane & 15)) * A_ROW_B + ((lane >> 4) << 4));
    uint32_t bAddr = (uint32_t)(F16_BH_B + (lane & 15) * B_ROW_B
                                + (wn + ((lane >> 4) << 3)) * 2);

    for (int c = 0; c < nk; c++) {
        CP_WAIT1();
        __syncthreads();
        load_stage(c + 2);

        uint32_t st = sb0 + (c % NSTAGE) * F16_STAGE_B;
#pragma unroll
        for (int ss = 0; ss < 2; ss++) {
            uint32_t ah[2][4], al[2][4], bh[4][2];
#pragma unroll
            for (int mt = 0; mt < 2; mt++) {
                uint32_t ao = st + aAddr + mt * 16 * A_ROW_B + ss * 32;
                ldsm4(ah[mt], ao);
                ldsm4(al[mt], ao + F16_AL_B);
            }
#pragma unroll
            for (int ntp = 0; ntp < 2; ntp++) {
                uint32_t bo = st + bAddr + ss * 16 * B_ROW_B + ntp * 32;
                ldsm4t(bh[2 * ntp][0], bh[2 * ntp][1],
                       bh[2 * ntp + 1][0], bh[2 * ntp + 1][1], bo);
            }
#pragma unroll
            for (int mt = 0; mt < 2; mt++)
#pragma unroll
                for (int nt = 0; nt < 4; nt++) mma16h(acc[mt][nt], ah[mt], bh[nt]);
#pragma unroll
            for (int mt = 0; mt < 2; mt++)
#pragma unroll
                for (int nt = 0; nt < 4; nt++) mma16h(acc[mt][nt], al[mt], bh[nt]);
        }
    }

    int row = lane >> 2, cc = lane & 3;
#pragma unroll
    for (int mt = 0; mt < 2; mt++) {
#pragma unroll
        for (int h = 0; h < 2; h++) {
            int r = m0 + wm + mt * 16 + row + h * 8;
#pragma unroll
            for (int nt = 0; nt < 4; nt++) {
#pragma unroll
                for (int j = 0; j < 2; j++) {
                    int cn = n0 + wn + nt * 8 + cc * 2 + j;
                    out[(size_t)r * N + cn] = acc[mt][nt][h * 2 + j];
                }
            }
        }
    }
}

// ---------------- fused embed + ln1(layer0) ----------------
__global__ void embed_ln_kernel(const int* __restrict__ ids, const float* __restrict__ emb,
                                const float* __restrict__ g, const float* __restrict__ b) {
    int row = blockIdx.x;
    int t = threadIdx.x;
    const float* src = emb + (size_t)ids[row] * DIM;
    float v0 = src[t], v1 = src[t + 256], v2 = src[t + 512];
    size_t base = (size_t)row * DIM;
    g_x[base + t] = v0; g_x[base + t + 256] = v1; g_x[base + t + 512] = v2;
    __shared__ float red[256];
    red[t] = v0 + v1 + v2;
    __syncthreads();
    for (int o = 128; o > 0; o >>= 1) { if (t < o) red[t] += red[t + o]; __syncthreads(); }
    float mean = red[0] * (1.0f / DIM);
    __syncthreads();
    float d0 = v0 - mean, d1 = v1 - mean, d2 = v2 - mean;
    red[t] = d0 * d0 + d1 * d1 + d2 * d2;
    __syncthreads();
    for (int o = 128; o > 0; o >>= 1) { if (t < o) red[t] += red[t + o]; __syncthreads(); }
    float rstd = rsqrtf(red[0] * (1.0f / DIM) + 1e-6f);
#pragma unroll
    for (int i = 0; i < 3; i++) {
        int d = t + i * 256;
        float dv = (i == 0 ? d0 : (i == 1 ? d1 : d2));
        float val = dv * rstd * g[d] + b[d];
        g_h[base + d] = val;
        float hi, lo;
        split_bf(val, hi, lo);
        g_hh[base + d] = __float2bfloat16_rn(hi);
        g_hl[base + d] = __float2bfloat16_rn(lo);
    }
}

// ---------------- layernorm over g_x (ln2 after wo); zeroes counts ----------------
__global__ void ln_kernel(const float* __restrict__ g, const float* __restrict__ b) {
    int row = blockIdx.x;
    int t = threadIdx.x;
    if (row == 0 && t < NE) g_counts[t] = 0;
    const float* xr = g_x + (size_t)row * DIM;
    float v0 = xr[t], v1 = xr[t + 256], v2 = xr[t + 512];
    __shared__ float red[256];
    red[t] = v0 + v1 + v2;
    __syncthreads();
    for (int o = 128; o > 0; o >>= 1) { if (t < o) red[t] += red[t + o]; __syncthreads(); }
    float mean = red[0] * (1.0f / DIM);
    __syncthreads();
    float d0 = v0 - mean, d1 = v1 - mean, d2 = v2 - mean;
    red[t] = d0 * d0 + d1 * d1 + d2 * d2;
    __syncthreads();
    for (int o = 128; o > 0; o >>= 1) { if (t < o) red[t] += red[t + o]; __syncthreads(); }
    float rstd = rsqrtf(red[0] * (1.0f / DIM) + 1e-6f);
    size_t base = (size_t)row * DIM;
#pragma unroll
    for (int i = 0; i < 3; i++) {
        int d = t + i * 256;
        float dv = (i == 0 ? d0 : (i == 1 ? d1 : d2));
        float val = dv * rstd * g[d] + b[d];
        g_h[base + d] = val;
        float hi, lo;
        split_bf(val, hi, lo);
        g_hh[base + d] = __float2bfloat16_rn(hi);
        g_hl[base + d] = __float2bfloat16_rn(lo);
    }
}

// ---------------- fused MoE scatter + next layernorm ----------------
// fp16mode: write fp16 hi/lo (for fp16 LM head) instead of bf16.
__global__ void scatter_ln_kernel(const float* __restrict__ g, const float* __restrict__ b,
                                  int fp16mode) {
    int row = blockIdx.x;
    int t = threadIdx.x;
    int r0 = g_perm[2 * row], r1 = g_perm[2 * row + 1];
    float w0 = g_roww[r0], w1 = g_roww[r1];
    size_t base = (size_t)row * DIM;
    const float* y0 = g_yff + (size_t)r0 * DIM;
    const float* y1 = g_yff + (size_t)r1 * DIM;
    float v[3];
#pragma unroll
    for (int i = 0; i < 3; i++) {
        int d = t + i * 256;
        v[i] = g_x[base + d] + w0 * y0[d] + w1 * y1[d];
        g_x[base + d] = v[i];
    }
    __shared__ float red[256];
    red[t] = v[0] + v[1] + v[2];
    __syncthreads();
    for (int o = 128; o > 0; o >>= 1) { if (t < o) red[t] += red[t + o]; __syncthreads(); }
    float mean = red[0] * (1.0f / DIM);
    __syncthreads();
    float d0 = v[0] - mean, d1 = v[1] - mean, d2 = v[2] - mean;
    red[t] = d0 * d0 + d1 * d1 + d2 * d2;
    __syncthreads();
    for (int o = 128; o > 0; o >>= 1) { if (t < o) red[t] += red[t + o]; __syncthreads(); }
    float rstd = rsqrtf(red[0] * (1.0f / DIM) + 1e-6f);
#pragma unroll
    for (int i = 0; i < 3; i++) {
        int d = t + i * 256;
        float dv = (i == 0 ? d0 : (i == 1 ? d1 : d2));
        float val = dv * rstd * g[d] + b[d];
        if (fp16mode) {
            __half hh = __float2half_rn(val);
            ((__half*)g_hh)[base + d] = hh;
            ((__half*)g_hl)[base + d] = __float2half_rn(val - __half2float(hh));
        } else {
            g_h[base + d] = val;
            float hi, lo;
            split_bf(val, hi, lo);
            g_hh[base + d] = __float2bfloat16_rn(hi);
            g_hl[base + d] = __float2bfloat16_rn(lo);
        }
    }
}

// ---------------- RoPE on q and k (in place) ----------------
__global__ void rope_kernel() {
    int idx = blockIdx.x * blockDim.x + threadIdx.x;
    if (idx >= TB * NH * 32) return;
    int j = idx & 31;
    int h = (idx >> 5) % NH;
    int t = idx / (32 * NH);
    int s = t % SEQ;
    float inv = exp2f(-(float)j * 0.41524101186092029f);
    float ang = (float)s * inv;
    float sn, cs;
    sincosf(ang, &sn, &cs);
    int base = t * DIM + h * HD;
    float a = g_q[base + j], b2 = g_q[base + 32 + j];
    g_q[base + j]      = a * cs - b2 * sn;
    g_q[base + 32 + j] = b2 * cs + a * sn;
    a = g_k[base + j]; b2 = g_k[base + 32 + j];
    g_k[base + j]      = a * cs - b2 * sn;
    g_k[base + 32 + j] = b2 * cs + a * sn;
}

// =====================================================================
//  flash attention (fp32, smem-tiled)
// =====================================================================
#define AQ 64
#define AKT 32
#define KVS 68
#define AQS_F (AQ * HD)
#define KVBUF_F (AKT * KVS)
#define KVSTG_F (2 * KVBUF_F)
#define ASMEM ((AQS_F + 2 * KVSTG_F) * 4)

__global__ void __launch_bounds__(256, 2) attn_kernel() {
    extern __shared__ float sm[];
    float* Qs = sm;
    float* KV = sm + AQS_F;
    const uint32_t kvu = smem_u32(KV);

    int tid = threadIdx.x, lane = tid & 31, w = tid >> 5;
    int qb = 15 - blockIdx.x;
    int bh = blockIdx.y;
    int b = bh / NH, h = bh % NH;
    int q0 = qb * AQ;
    size_t kvbase = ((size_t)b * SEQ) * DIM + h * HD;

    {
        const float* qsrc = g_q + ((size_t)(b * SEQ + q0)) * DIM + h * HD;
#pragma unroll
        for (int i = 0; i < 4; i++) {
            int e4 = tid + i * 256;
            int r = e4 >> 4, dq = (e4 & 15) * 4;
            float4 v = *(const float4*)(qsrc + (size_t)r * DIM + dq);
            v.x *= 0.125f; v.y *= 0.125f; v.z *= 0.125f; v.w *= 0.125f;
            *(float4*)(Qs + r * HD + dq) = v;
        }
    }

    const int nt = 2 * qb + 2;

    auto load_tile = [&](int t) {
        uint32_t dstb = kvu + (t & 1) * (KVSTG_F * 4);
#pragma unroll
        for (int i = 0; i < 2; i++) {
            int c = tid + i * 256;
            int r = c >> 4, of = (c & 15) * 4;
            size_t src = kvbase + (size_t)(t * AKT + r) * DIM + of;
            uint32_t d = dstb + (r * KVS + of) * 4;
            cpa16f(d, g_k + src);
            cpa16f(d + KVBUF_F * 4, g_v + src);
        }
        CP_COMMIT();
    };

    float m[8], l[8], a0[8], a1[8], sc[8];
#pragma unroll
    for (int q = 0; q < 8; q++) { m[q] = -1e30f; l[q] = 0.f; a0[q] = 0.f; a1[q] = 0.f; }

    const float* qsw = Qs + (w * 8) * HD;
    int qg0 = q0 + w * 8;

    load_tile(0);

    for (int t = 0; t < nt; t++) {
        if (t + 1 < nt) load_tile(t + 1); else CP_COMMIT();
        CP_WAIT1();
        __syncthreads();

        const float* Ksb = KV + (t & 1) * KVSTG_F;
        const float* Vsb = Ksb + KVBUF_F;

#pragma unroll
        for (int q = 0; q < 8; q++) sc[q] = 0.f;
#pragma unroll
        for (int dq = 0; dq < 16; dq++) {
            float4 kv = *(const float4*)(Ksb + lane * KVS + dq * 4);
#pragma unroll
            for (int q = 0; q < 8; q++) {
                float4 qv = *(const float4*)(qsw + q * HD + dq * 4);
                sc[q] += qv.x * kv.x + qv.y * kv.y + qv.z * kv.z + qv.w * kv.w;
            }
        }
        if (t >= nt - 2) {
            int kg = t * AKT + lane;
#pragma unroll
            for (int q = 0; q < 8; q++)
                if (kg > qg0 + q) sc[q] = -1e30f;
        }

#pragma unroll
        for (int q = 0; q < 8; q++) {
            float tm = sc[q];
#pragma unroll
            for (int o = 16; o; o >>= 1) tm = fmaxf(tm, __shfl_xor_sync(0xffffffffu, tm, o));
            float mn = fmaxf(m[q], tm);
            float corr = __expf(m[q] - mn);
            float p = __expf(sc[q] - mn);
            float ps = p;
#pragma unroll
            for (int o = 16; o; o >>= 1) ps += __shfl_xor_sync(0xffffffffu, ps, o);
            l[q] = l[q] * corr + ps;
            m[q] = mn;
            a0[q] *= corr;
            a1[q] *= corr;
            sc[q] = p;
        }

#pragma unroll
        for (int kk = 0; kk < AKT; kk++) {
            float v0 = Vsb[kk * KVS + lane];
            float v1 = Vsb[kk * KVS + lane + 32];
#pragma unroll
            for (int q = 0; q < 8; q++) {
                float pq = __shfl_sync(0xffffffffu, sc[q], kk);
                a0[q] += pq * v0;
                a1[q] += pq * v1;
            }
        }
        __syncthreads();
    }

#pragma unroll
    for (int q = 0; q < 8; q++) {
        float inv = 1.0f / l[q];
        float o0 = a0[q] * inv, o1 = a1[q] * inv;
        size_t ob = ((size_t)(b * SEQ + qg0 + q)) * DIM + h * HD;
        bf16 h0 = __float2bfloat16_rn(o0);
        bf16 h1 = __float2bfloat16_rn(o1);
        g_aoh[ob + lane] = h0;
        g_aol[ob + lane] = __float2bfloat16_rn(o0 - __bfloat162float(h0));
        g_aoh[ob + lane + 32] = h1;
        g_aol[ob + lane + 32] = __float2bfloat16_rn(o1 - __bfloat162float(h1));
    }
}

// ---------------- fused MoE gate + top-2 (counts zeroed in ln_kernel) --------
__global__ void gate_topk_kernel(const float* __restrict__ Wg) {
    int tok = blockIdx.x;
    int e = threadIdx.x >> 5;
    int lane = threadIdx.x & 31;
    __shared__ float lgs[NE];
    const float* hr = g_h + (size_t)tok * DIM;
    float s = 0.f;
    for (int d = lane; d < DIM; d += 32) s += hr[d] * Wg[d * NE + e];
#pragma unroll
    for (int o = 16; o; o >>= 1) s += __shfl_xor_sync(0xffffffffu, s, o);
    if (lane == 0) lgs[e] = s;
    __syncthreads();
    if (threadIdx.x == 0) {
        float lg[NE];
        float m = -1e30f;
#pragma unroll
        for (int i = 0; i < NE; i++) { lg[i] = lgs[i]; m = fmaxf(m, lg[i]); }
        float ssum = 0.f;
#pragma unroll
        for (int i = 0; i < NE; i++) { lg[i] = expf(lg[i] - m); ssum += lg[i]; }
        int i0 = 0;
#pragma unroll
        for (int i = 1; i < NE; i++) if (lg[i] > lg[i0]) i0 = i;
        int i1 = (i0 == 0) ? 1 : 0;
#pragma unroll
        for (int i = 0; i < NE; i++) if (i != i0 && i != i1 && lg[i] > lg[i1]) i1 = i;
        float v0 = lg[i0] / ssum, v1 = lg[i1] / ssum;
        float winv = 1.0f / (v0 + v1);
        g_te[2 * tok] = i0; g_te[2 * tok + 1] = i1;
        g_tw[2 * tok] = v0 * winv; g_tw[2 * tok + 1] = v1 * winv;
        atomicAdd(&g_counts[i0], 1);
        atomicAdd(&g_counts[i1], 1);
    }
}

// ---------------- fused scan + assign (single block) ----------------
__global__ void scan_assign_kernel() {
    __shared__ int soff[NE];
    __shared__ int scur[NE];
    if (threadIdx.x == 0) {
        int acc = 0;
        for (int e = 0; e < NE; e++) {
            soff[e] = acc;
            g_offsets[e] = acc;
            acc += g_counts[e];
            scur[e] = 0;
        }
    }
    __syncthreads();
    for (int t = threadIdx.x; t < TB; t += blockDim.x) {
#pragma unroll
        for (int kk = 0; kk < 2; kk++) {
            int e = g_te[2 * t + kk];
            int pos = soff[e] + atomicAdd(&scur[e], 1);
            g_rowtok[pos] = t;
            g_roww[pos] = g_tw[2 * t + kk];
            g_perm[2 * t + kk] = pos;
        }
    }
}

// ---------------- host orchestration ----------------
extern "C" void kernel_launch(void* const* d_in, const int* in_sizes, int n_in,
                              void* d_out, int out_size) {
    (void)in_sizes; (void)n_in; (void)out_size;
    const int*   ids   = (const int*)  d_in[0];
    const float* emb   = (const float*)d_in[1];
    const float* ln1_g = (const float*)d_in[2];
    const float* ln1_b = (const float*)d_in[3];
    const float* ln2_g = (const float*)d_in[4];
    const float* ln2_b = (const float*)d_in[5];
    const float* Wq    = (const float*)d_in[6];
    const float* Wkv   = (const float*)d_in[7];
    const float* Wk    = (const float*)d_in[8];
    const float* Wv    = (const float*)d_in[9];
    const float* Wo    = (const float*)d_in[10];
    const float* Wg    = (const float*)d_in[11];
    const float* W1    = (const float*)d_in[12];
    const float* b1    = (const float*)d_in[13];
    const float* W2    = (const float*)d_in[14];
    const float* b2    = (const float*)d_in[15];
    const float* lnf_g = (const float*)d_in[16];
    const float* lnf_b = (const float*)d_in[17];
    const float* Wout  = (const float*)d_in[18];

    cudaFuncSetAttribute(qkv1_kernel,  cudaFuncAttributeMaxDynamicSharedMemorySize, GSMEM);
    cudaFuncSetAttribute(kv2_kernel,   cudaFuncAttributeMaxDynamicSharedMemorySize, GSMEM);
    cudaFuncSetAttribute(wo_kernel,    cudaFuncAttributeMaxDynamicSharedMemorySize, GSMEM);
    cudaFuncSetAttribute(moe1_kernel,  cudaFuncAttributeMaxDynamicSharedMemorySize, GSMEM);
    cudaFuncSetAttribute(moe2_kernel,  cudaFuncAttributeMaxDynamicSharedMemorySize, GSMEM);
    cudaFuncSetAttribute(lmhead_kernel, cudaFuncAttributeMaxDynamicSharedMemorySize, GSMEM16);
    cudaFuncSetAttribute(attn_kernel,  cudaFuncAttributeMaxDynamicSharedMemorySize, ASMEM);

    bf16 *wqh, *wql, *wkvh, *wkvl, *wkh, *wkl, *wvh, *wvl, *woh, *wol,
         *w1h, *w1l, *w2h, *w2l;
    __half* wouth;
    cudaGetSymbolAddress((void**)&wqh,  g_wqh);  cudaGetSymbolAddress((void**)&wql,  g_wql);
    cudaGetSymbolAddress((void**)&wkvh, g_wkvh); cudaGetSymbolAddress((void**)&wkvl, g_wkvl);
    cudaGetSymbolAddress((void**)&wkh,  g_wkh);  cudaGetSymbolAddress((void**)&wkl,  g_wkl);
    cudaGetSymbolAddress((void**)&wvh,  g_wvh);  cudaGetSymbolAddress((void**)&wvl,  g_wvl);
    cudaGetSymbolAddress((void**)&woh,  g_woh);  cudaGetSymbolAddress((void**)&wol,  g_wol);
    cudaGetSymbolAddress((void**)&w1h,  g_w1h);  cudaGetSymbolAddress((void**)&w1l,  g_w1l);
    cudaGetSymbolAddress((void**)&w2h,  g_w2h);  cudaGetSymbolAddress((void**)&w2l,  g_w2l);
    cudaGetSymbolAddress((void**)&wouth, g_wouth);

    auto wc = [&](const float* s, bf16* h, bf16* l, size_t n) {
        int n4 = (int)(n / 4);
        wconv_kernel<<<(n4 + 255) / 256, 256>>>(s, h, l, n4);
    };

    // Launch order: 1-based #4 = qkv1 (ncu captures launch #4).
    embed_ln_kernel<<<TB, 256>>>(ids, emb, ln1_g, ln1_b);                     // 1
    wc(Wq, wqh, wql, (size_t)NLAYER * DIM * DIM);                             // 2
    {
        int n4 = NLAYER * DIM * DLAT / 4;                                     // 3
        wconv3_kernel<<<dim3((n4 + 255) / 256, 3), 256>>>(
            Wkv, wkvh, wkvl, Wk, wkh, wkl, Wv, wvh, wvl, n4);
    }

    for (int l = 0; l < NLAYER; l++) {
        // --- attention block ---
        qkv1_kernel<<<dim3(15, TB / 128), 256, GSMEM>>>(l);                   // 4 (l==0)
        kv2_kernel<<<dim3(24, TB / 128), 256, GSMEM>>>(l);
        rope_kernel<<<(TB * NH * 32 + 255) / 256, 256>>>();
        attn_kernel<<<dim3(SEQ / AQ, BATCH * NH), 256, ASMEM>>>();
        if (l == 0) {
            wc(Wo, woh, wol, (size_t)NLAYER * DIM * DIM);
            wc(W1, w1h, w1l, (size_t)NLAYER * NE * DIM * DFF);
            wc(W2, w2h, w2l, (size_t)NLAYER * NE * DFF * DIM);
            int n4o = DIM * NV / 4;
            wconvh_kernel<<<(n4o + 255) / 256, 256>>>(Wout, wouth, n4o);
        }
        wo_kernel<<<dim3(DIM / 64, TB / 128), 256, GSMEM>>>(l);

        // --- MoE block ---
        ln_kernel<<<TB, 256>>>(ln2_g + l * DIM, ln2_b + l * DIM);
        gate_topk_kernel<<<TB, 256>>>(Wg + (size_t)l * DIM * NE);
        scan_assign_kernel<<<1, 1024>>>();
        moe1_kernel<<<dim3(DFF / 64, 2 * TB / 128, NE), 256, GSMEM>>>(b1, l);
        moe2_kernel<<<dim3(DIM / 64, 2 * TB / 128, NE), 256, GSMEM>>>(b2, l);

        // --- fused scatter + next LN ---
        if (l + 1 < NLAYER)
            scatter_ln_kernel<<<TB, 256>>>(ln1_g + (l + 1) * DIM, ln1_b + (l + 1) * DIM, 0);
        else
            scatter_ln_kernel<<<TB, 256>>>(lnf_g, lnf_b, 1);   // fp16 hi/lo for LM head
    }

    // --- LM head (fp16 2-pass) ---
    lmhead_kernel<<<dim3(NV / 64, TB / 128), 256, GSMEM16>>>((float*)d_out);
}

// round 14
// speedup vs baseline: 1.5363x; 1.5363x over previous
#include <cuda_runtime.h>
#include <cuda_bf16.h>
#include <cuda_fp16.h>
#include <math.h>
#include <stdint.h>

// ---------------- problem dims ----------------
#define TB 2048
#define SEQ 1024
#define BATCH 2
#define DIM 768
#define NH 12
#define HD 64
#define DLAT 192
#define DFF 3072
#define NE 8
#define NV 32000
#define NLAYER 2

#define FLAG_ACC 1
#define FLAG_GELU 2

typedef __nv_bfloat16 bf16;

// ---------------- fp32 scratch ----------------
__device__ float g_x[TB * DIM];
__device__ float g_h[TB * DIM];
__device__ float g_q[TB * DIM];
__device__ float g_k[TB * DIM];
__device__ float g_v[TB * DIM];
__device__ float g_yff[2 * TB * DIM];
__device__ float g_logits[TB * NE];
__device__ float g_tw[TB * 2];
__device__ int   g_te[TB * 2];
__device__ int   g_counts[NE];
__device__ int   g_offsets[NE];
__device__ int   g_cursor[NE];
__device__ int   g_rowtok[2 * TB];
__device__ float g_roww[2 * TB];
__device__ int   g_perm[2 * TB];

// ---------------- bf16 (or fp16, final layer) hi/lo activations ----------------
__device__ bf16 g_hh[TB * DIM],  g_hl[TB * DIM];
__device__ bf16 g_lath[TB * DLAT], g_latl[TB * DLAT];
__device__ bf16 g_aoh[TB * DIM], g_aol[TB * DIM];
__device__ bf16 g_hffh[2 * TB * DFF], g_hffl[2 * TB * DFF];

// ---------------- bf16 hi/lo weights (+ fp16 Wout) ----------------
__device__ bf16 g_wqh[NLAYER * DIM * DIM],  g_wql[NLAYER * DIM * DIM];
__device__ bf16 g_wkvh[NLAYER * DIM * DLAT], g_wkvl[NLAYER * DIM * DLAT];
__device__ bf16 g_wkh[NLAYER * DLAT * DIM], g_wkl[NLAYER * DLAT * DIM];
__device__ bf16 g_wvh[NLAYER * DLAT * DIM], g_wvl[NLAYER * DLAT * DIM];
__device__ bf16 g_woh[NLAYER * DIM * DIM],  g_wol[NLAYER * DIM * DIM];
__device__ bf16 g_w1h[NLAYER * NE * DIM * DFF], g_w1l[NLAYER * NE * DIM * DFF];
__device__ bf16 g_w2h[NLAYER * NE * DFF * DIM], g_w2l[NLAYER * NE * DFF * DIM];
__device__ __half g_wouth[DIM * NV];

// ---------------- helpers ----------------
__device__ __forceinline__ uint32_t smem_u32(const void* p) {
    uint32_t a;
    asm("{ .reg .u64 t; cvta.to.shared.u64 t, %1; cvt.u32.u64 %0, t; }" : "=r"(a) : "l"(p));
    return a;
}
__device__ __forceinline__ uint32_t pack_bf2(float a, float b) {
    __nv_bfloat162 h = __floats2bfloat162_rn(a, b);
    return *(uint32_t*)&h;
}
__device__ __forceinline__ void split_bf(float x, float& hi, float& lo) {
    bf16 h = __float2bfloat16_rn(x);
    hi = __bfloat162float(h);
    lo = x - hi;
}
__device__ __forceinline__ float gelu_f(float x) {
    const float k0 = 0.7978845608028654f;
    float x3 = x * x * x;
    return 0.5f * x * (1.0f + tanhf(k0 * (x + 0.044715f * x3)));
}
__device__ __forceinline__ void mma16(float d[4], const uint32_t a[4], const uint32_t b[2]) {
    asm volatile(
        "mma.sync.aligned.m16n8k16.row.col.f32.bf16.bf16.f32 "
        "{%0,%1,%2,%3},{%4,%5,%6,%7},{%8,%9},{%0,%1,%2,%3};"
        : "+f"(d[0]), "+f"(d[1]), "+f"(d[2]), "+f"(d[3])
        : "r"(a[0]), "r"(a[1]), "r"(a[2]), "r"(a[3]),
          "r"(b[0]), "r"(b[1]));
}
__device__ __forceinline__ void mma16h(float d[4], const uint32_t a[4], const uint32_t b[2]) {
    asm volatile(
        "mma.sync.aligned.m16n8k16.row.col.f32.f16.f16.f32 "
        "{%0,%1,%2,%3},{%4,%5,%6,%7},{%8,%9},{%0,%1,%2,%3};"
        : "+f"(d[0]), "+f"(d[1]), "+f"(d[2]), "+f"(d[3])
        : "r"(a[0]), "r"(a[1]), "r"(a[2]), "r"(a[3]),
          "r"(b[0]), "r"(b[1]));
}
__device__ __forceinline__ void ldsm4(uint32_t r[4], uint32_t addr) {
    asm volatile("ldmatrix.sync.aligned.m8n8.x4.shared.b16 {%0,%1,%2,%3}, [%4];"
                 : "=r"(r[0]), "=r"(r[1]), "=r"(r[2]), "=r"(r[3]) : "r"(addr));
}
__device__ __forceinline__ void ldsm4t(uint32_t& r0, uint32_t& r1, uint32_t& r2,
                                       uint32_t& r3, uint32_t addr) {
    asm volatile("ldmatrix.sync.aligned.m8n8.x4.trans.shared.b16 {%0,%1,%2,%3}, [%4];"
                 : "=r"(r0), "=r"(r1), "=r"(r2), "=r"(r3) : "r"(addr));
}
__device__ __forceinline__ void cpa16(uint32_t dst, const void* src, int sz) {
    asm volatile("cp.async.cg.shared.global [%0], [%1], 16, %2;"
                 :: "r"(dst), "l"(src), "r"(sz) : "memory");
}
__device__ __forceinline__ void cpa16f(uint32_t dst, const void* src) {
    asm volatile("cp.async.cg.shared.global [%0], [%1], 16;"
                 :: "r"(dst), "l"(src) : "memory");
}
#define CP_COMMIT() asm volatile("cp.async.commit_group;" ::: "memory")
#define CP_WAIT1()  asm volatile("cp.async.wait_group 1;" ::: "memory")

// ---------------- weight fp32 -> bf16 hi/lo conversion ----------------
__device__ __forceinline__ void wconv_body(const float* __restrict__ s,
                                           bf16* __restrict__ h, bf16* __restrict__ l,
                                           int i, int n4) {
    if (i >= n4) return;
    float4 v = ((const float4*)s)[i];
    float h0, l0, h1, l1, h2, l2, h3, l3;
    split_bf(v.x, h0, l0); split_bf(v.y, h1, l1);
    split_bf(v.z, h2, l2); split_bf(v.w, h3, l3);
    ((uint2*)h)[i] = make_uint2(pack_bf2(h0, h1), pack_bf2(h2, h3));
    ((uint2*)l)[i] = make_uint2(pack_bf2(l0, l1), pack_bf2(l2, l3));
}

__global__ void wconv_kernel(const float* __restrict__ s, bf16* __restrict__ h,
                             bf16* __restrict__ l, int n4) {
    wconv_body(s, h, l, blockIdx.x * blockDim.x + threadIdx.x, n4);
}

__global__ void wconv3_kernel(const float* __restrict__ s0, bf16* __restrict__ h0, bf16* __restrict__ l0,
                              const float* __restrict__ s1, bf16* __restrict__ h1, bf16* __restrict__ l1,
                              const float* __restrict__ s2, bf16* __restrict__ h2, bf16* __restrict__ l2,
                              int n4) {
    const float* s; bf16 *h, *l;
    if (blockIdx.y == 0)      { s = s0; h = h0; l = l0; }
    else if (blockIdx.y == 1) { s = s1; h = h1; l = l1; }
    else                      { s = s2; h = h2; l = l2; }
    wconv_body(s, h, l, blockIdx.x * blockDim.x + threadIdx.x, n4);
}

// fp32 -> fp16 (hi only, for Wout)
__global__ void wconvh_kernel(const float* __restrict__ s, __half* __restrict__ h, int n4) {
    int i = blockIdx.x * blockDim.x + threadIdx.x;
    if (i >= n4) return;
    float4 v = ((const float4*)s)[i];
    __half2 p0 = __floats2half2_rn(v.x, v.y);
    __half2 p1 = __floats2half2_rn(v.z, v.w);
    ((uint2*)h)[i] = make_uint2(*(uint32_t*)&p0, *(uint32_t*)&p1);
}

// =====================================================================
//   bf16x3 mma.sync GEMM, cp.async 3-stage pipeline, ldmatrix(.trans)
// =====================================================================
#define A_ROW_B 80
#define B_ROW_B 144
#define AL_B 10240
#define BH_B 20480
#define BL_B 25088
#define STAGE_B 29696
#define NSTAGE 3
#define GSMEM (STAGE_B * NSTAGE)

__device__ __forceinline__ void gemm_tile(
    const bf16* __restrict__ Ah, const bf16* __restrict__ Al,
    const int* __restrict__ Aidx,
    const bf16* __restrict__ Bh, const bf16* __restrict__ Bl,
    const float* __restrict__ bias,
    float* __restrict__ C, bf16* __restrict__ Chi, bf16* __restrict__ Clo,
    int Mv, int N, int K, int m0, int n0, int flags)
{
    extern __shared__ uint32_t smu[];
    const uint32_t sb0 = smem_u32(smu);
    int tid = threadIdx.x, lane = tid & 31, warp = tid >> 5;
    int wm = (warp >> 1) * 32, wn = (warp & 1) * 32;

    int jA = tid & 3, rA = tid >> 2;
    int kB = tid >> 3, jB = tid & 7;
    int gmr0 = m0 + rA, gmr1 = m0 + rA + 64;
    int szA0 = gmr0 < Mv ? 16 : 0;
    int szA1 = gmr1 < Mv ? 16 : 0;
    int row0 = gmr0 < Mv ? (Aidx ? Aidx[gmr0] : gmr0) : 0;
    int row1 = gmr1 < Mv ? (Aidx ? Aidx[gmr1] : gmr1) : 0;
    const bf16* pAh0 = Ah + (size_t)row0 * K + jA * 8;
    const bf16* pAl0 = Al + (size_t)row0 * K + jA * 8;
    const bf16* pAh1 = Ah + (size_t)row1 * K + jA * 8;
    const bf16* pAl1 = Al + (size_t)row1 * K + jA * 8;
    const bf16* pBh = Bh + (size_t)kB * N + n0 + jB * 8;
    const bf16* pBl = Bl + (size_t)kB * N + n0 + jB * 8;
    uint32_t dA0 = rA * A_ROW_B + jA * 16;
    uint32_t dA1 = dA0 + 64 * A_ROW_B;
    uint32_t dB  = kB * B_ROW_B + jB * 16;

    const int nk = K / 32;

    auto load_stage = [&](int c) {
        if (c < nk) {
            uint32_t st = sb0 + (c % NSTAGE) * STAGE_B;
            int kc = c * 32;
            size_t bo = (size_t)kc * N;
            cpa16(st + dA0, pAh0 + kc, szA0);
            cpa16(st + dA1, pAh1 + kc, szA1);
            cpa16(st + AL_B + dA0, pAl0 + kc, szA0);
            cpa16(st + AL_B + dA1, pAl1 + kc, szA1);
            cpa16(st + BH_B + dB, pBh + bo, 16);
            cpa16(st + BL_B + dB, pBl + bo, 16);
        }
        CP_COMMIT();
    };

    float acc[2][4][4] = {};

    load_stage(0);
    load_stage(1);

    uint32_t aAddr = (uint32_t)((wm + (lane & 15)) * A_ROW_B + ((lane >> 4) << 4));
    uint32_t bAddr = (uint32_t)(BH_B + (lane & 15) * B_ROW_B
                                + (wn + ((lane >> 4) << 3)) * 2);

    for (int c = 0; c < nk; c++) {
        CP_WAIT1();
        __syncthreads();
        load_stage(c + 2);

        uint32_t st = sb0 + (c % NSTAGE) * STAGE_B;
#pragma unroll
        for (int ss = 0; ss < 2; ss++) {
            uint32_t ah[2][4], al[2][4], bh[4][2], bl[4][2];
#pragma unroll
            for (int mt = 0; mt < 2; mt++) {
                uint32_t ao = st + aAddr + mt * 16 * A_ROW_B + ss * 32;
                ldsm4(ah[mt], ao);
                ldsm4(al[mt], ao + AL_B);
            }
#pragma unroll
            for (int ntp = 0; ntp < 2; ntp++) {
                uint32_t bo = st + bAddr + ss * 16 * B_ROW_B + ntp * 32;
                ldsm4t(bh[2 * ntp][0], bh[2 * ntp][1],
                       bh[2 * ntp + 1][0], bh[2 * ntp + 1][1], bo);
                ldsm4t(bl[2 * ntp][0], bl[2 * ntp][1],
                       bl[2 * ntp + 1][0], bl[2 * ntp + 1][1], bo + (BL_B - BH_B));
            }
#pragma unroll
            for (int mt = 0; mt < 2; mt++)
#pragma unroll
                for (int nt = 0; nt < 4; nt++) mma16(acc[mt][nt], ah[mt], bh[nt]);
#pragma unroll
            for (int mt = 0; mt < 2; mt++)
#pragma unroll
                for (int nt = 0; nt < 4; nt++) mma16(acc[mt][nt], ah[mt], bl[nt]);
#pragma unroll
            for (int mt = 0; mt < 2; mt++)
#pragma unroll
                for (int nt = 0; nt < 4; nt++) mma16(acc[mt][nt], al[mt], bh[nt]);
        }
    }

    int row = lane >> 2, cc = lane & 3;
#pragma unroll
    for (int mt = 0; mt < 2; mt++) {
#pragma unroll
        for (int h = 0; h < 2; h++) {
            int r = m0 + wm + mt * 16 + row + h * 8;
            if (r >= Mv) continue;
#pragma unroll
            for (int nt = 0; nt < 4; nt++) {
#pragma unroll
                for (int j = 0; j < 2; j++) {
                    int cn = n0 + wn + nt * 8 + cc * 2 + j;
                    float val = acc[mt][nt][h * 2 + j];
                    if (bias) val += bias[cn];
                    if (flags & FLAG_GELU) val = gelu_f(val);
                    size_t ix = (size_t)r * N + cn;
                    if (flags & FLAG_ACC) C[ix] += val;
                    else if (C) C[ix] = val;
                    if (Chi) {
                        bf16 hv = __float2bfloat16_rn(val);
                        Chi[ix] = hv;
                        Clo[ix] = __float2bfloat16_rn(val - __bfloat162float(hv));
                    }
                }
            }
        }
    }
}

__global__ void __launch_bounds__(256, 2) qkv1_kernel(int l) {
    int bx = blockIdx.x;
    size_t wq = (size_t)l * DIM * DIM, wkv = (size_t)l * DIM * DLAT;
    if (bx < 12)
        gemm_tile(g_hh, g_hl, nullptr, g_wqh + wq, g_wql + wq, nullptr,
                  g_q, nullptr, nullptr, TB, DIM, DIM, blockIdx.y * 128, bx * 64, 0);
    else
        gemm_tile(g_hh, g_hl, nullptr, g_wkvh + wkv, g_wkvl + wkv, nullptr,
                  nullptr, g_lath, g_latl, TB, DLAT, DIM,
                  blockIdx.y * 128, (bx - 12) * 64, 0);
}

__global__ void __launch_bounds__(256, 2) kv2_kernel(int l) {
    int bx = blockIdx.x;
    size_t w = (size_t)l * DLAT * DIM;
    if (bx < 12)
        gemm_tile(g_lath, g_latl, nullptr, g_wkh + w, g_wkl + w, nullptr,
                  g_k, nullptr, nullptr, TB, DIM, DLAT, blockIdx.y * 128, bx * 64, 0);
    else
        gemm_tile(g_lath, g_latl, nullptr, g_wvh + w, g_wvl + w, nullptr,
                  g_v, nullptr, nullptr, TB, DIM, DLAT,
                  blockIdx.y * 128, (bx - 12) * 64, 0);
}

__global__ void __launch_bounds__(256, 2) wo_kernel(int l) {
    size_t w = (size_t)l * DIM * DIM;
    gemm_tile(g_aoh, g_aol, nullptr, g_woh + w, g_wol + w, nullptr,
              g_x, nullptr, nullptr, TB, DIM, DIM,
              blockIdx.y * 128, blockIdx.x * 64, FLAG_ACC);
}

__global__ void __launch_bounds__(256, 2) moe1_kernel(const float* __restrict__ b1, int l) {
    int e = blockIdx.z;
    int cnt = g_counts[e];
    int m0 = blockIdx.y * 128;
    if (m0 >= cnt) return;
    int off = g_offsets[e];
    size_t w = ((size_t)l * NE + e) * DIM * DFF;
    gemm_tile(g_hh, g_hl, g_rowtok + off, g_w1h + w, g_w1l + w,
              b1 + ((size_t)l * NE + e) * DFF,
              nullptr, g_hffh + (size_t)off * DFF, g_hffl + (size_t)off * DFF,
              cnt, DFF, DIM, m0, blockIdx.x * 64, FLAG_GELU);
}

__global__ void __launch_bounds__(256, 2) moe2_kernel(const float* __restrict__ b2, int l) {
    int e = blockIdx.z;
    int cnt = g_counts[e];
    int m0 = blockIdx.y * 128;
    if (m0 >= cnt) return;
    int off = g_offsets[e];
    size_t w = ((size_t)l * NE + e) * DFF * DIM;
    gemm_tile(g_hffh + (size_t)off * DFF, g_hffl + (size_t)off * DFF, nullptr,
              g_w2h + w, g_w2l + w, b2 + ((size_t)l * NE + e) * DIM,
              g_yff + (size_t)off * DIM, nullptr, nullptr,
              cnt, DIM, DFF, m0, blockIdx.x * 64, 0);
}

// =====================================================================
//  LM head: fp16 2-pass GEMM (A = lnf hi/lo fp16, B = Wout fp16)
//  D = (Ah + Al) @ Bh.  Stage: Ah 10240B | Al 10240B | Bh 4608B.
//  Round-12 grid orientation (x = n-blocks, y = m-blocks).
// =====================================================================
#define F16_AL_B 10240
#define F16_BH_B 20480
#define F16_STAGE_B 25088
#define GSMEM16 (F16_STAGE_B * NSTAGE)

__global__ void __launch_bounds__(256, 2) lmhead_kernel(float* __restrict__ out) {
    const __half* Ah = (const __half*)g_hh;
    const __half* Al = (const __half*)g_hl;
    const __half* Bh = g_wouth;
    const int N = NV, K = DIM;
    int m0 = blockIdx.y * 128, n0 = blockIdx.x * 64;

    extern __shared__ uint32_t smu[];
    const uint32_t sb0 = smem_u32(smu);
    int tid = threadIdx.x, lane = tid & 31, warp = tid >> 5;
    int wm = (warp >> 1) * 32, wn = (warp & 1) * 32;

    int jA = tid & 3, rA = tid >> 2;
    int kB = tid >> 3, jB = tid & 7;
    const __half* pAh0 = Ah + (size_t)(m0 + rA) * K + jA * 8;
    const __half* pAl0 = Al + (size_t)(m0 + rA) * K + jA * 8;
    const __half* pAh1 = pAh0 + (size_t)64 * K;
    const __half* pAl1 = pAl0 + (size_t)64 * K;
    const __half* pBh = Bh + (size_t)kB * N + n0 + jB * 8;
    uint32_t dA0 = rA * A_ROW_B + jA * 16;
    uint32_t dA1 = dA0 + 64 * A_ROW_B;
    uint32_t dB  = kB * B_ROW_B + jB * 16;

    const int nk = K / 32;

    auto load_stage = [&](int c) {
        if (c < nk) {
            uint32_t st = sb0 + (c % NSTAGE) * F16_STAGE_B;
            int kc = c * 32;
            cpa16f(st + dA0, pAh0 + kc);
            cpa16f(st + dA1, pAh1 + kc);
            cpa16f(st + F16_AL_B + dA0, pAl0 + kc);
            cpa16f(st + F16_AL_B + dA1, pAl1 + kc);
            cpa16f(st + F16_BH_B + dB, pBh + (size_t)kc * N);
        }
        CP_COMMIT();
    };

    float acc[2][4][4] = {};

    load_stage(0);
    load_stage(1);

    uint32_t aAddr = (uint32_t)((wm + (lane & 15)) * A_ROW_B + ((lane >> 4) << 4));
    uint32_t bAddr = (uint32_t)(F16_BH_B + (lane & 15) * B_ROW_B
                                + (wn + ((lane >> 4) << 3)) * 2);

    for (int c = 0; c < nk; c++) {
        CP_WAIT1();
        __syncthreads();
        load_stage(c + 2);

        uint32_t st = sb0 + (c % NSTAGE) * F16_STAGE_B;
#pragma unroll
        for (int ss = 0; ss < 2; ss++) {
            uint32_t ah[2][4], al[2][4], bh[4][2];
#pragma unroll
            for (int mt = 0; mt < 2; mt++) {
                uint32_t ao = st + aAddr + mt * 16 * A_ROW_B + ss * 32;
                ldsm4(ah[mt], ao);
                ldsm4(al[mt], ao + F16_AL_B);
            }
#pragma unroll
            for (int ntp = 0; ntp < 2; ntp++) {
                uint32_t bo = st + bAddr + ss * 16 * B_ROW_B + ntp * 32;
                ldsm4t(bh[2 * ntp][0], bh[2 * ntp][1],
                       bh[2 * ntp + 1][0], bh[2 * ntp + 1][1], bo);
            }
#pragma unroll
            for (int mt = 0; mt < 2; mt++)
#pragma unroll
                for (int nt = 0; nt < 4; nt++) mma16h(acc[mt][nt], ah[mt], bh[nt]);
#pragma unroll
            for (int mt = 0; mt < 2; mt++)
#pragma unroll
                for (int nt = 0; nt < 4; nt++) mma16h(acc[mt][nt], al[mt], bh[nt]);
        }
    }

    int row = lane >> 2, cc = lane & 3;
#pragma unroll
    for (int mt = 0; mt < 2; mt++) {
#pragma unroll
        for (int h = 0; h < 2; h++) {
            int r = m0 + wm + mt * 16 + row + h * 8;
#pragma unroll
            for (int nt = 0; nt < 4; nt++) {
#pragma unroll
                for (int j = 0; j < 2; j++) {
                    int cn = n0 + wn + nt * 8 + cc * 2 + j;
                    out[(size_t)r * N + cn] = acc[mt][nt][h * 2 + j];
                }
            }
        }
    }
}

// ---------------- fused embed + ln1(layer0) ----------------
__global__ void embed_ln_kernel(const int* __restrict__ ids, const float* __restrict__ emb,
                                const float* __restrict__ g, const float* __restrict__ b) {
    int row = blockIdx.x;
    int t = threadIdx.x;
    const float* src = emb + (size_t)ids[row] * DIM;
    float v0 = src[t], v1 = src[t + 256], v2 = src[t + 512];
    size_t base = (size_t)row * DIM;
    g_x[base + t] = v0; g_x[base + t + 256] = v1; g_x[base + t + 512] = v2;
    __shared__ float red[256];
    red[t] = v0 + v1 + v2;
    __syncthreads();
    for (int o = 128; o > 0; o >>= 1) { if (t < o) red[t] += red[t + o]; __syncthreads(); }
    float mean = red[0] * (1.0f / DIM);
    __syncthreads();
    float d0 = v0 - mean, d1 = v1 - mean, d2 = v2 - mean;
    red[t] = d0 * d0 + d1 * d1 + d2 * d2;
    __syncthreads();
    for (int o = 128; o > 0; o >>= 1) { if (t < o) red[t] += red[t + o]; __syncthreads(); }
    float rstd = rsqrtf(red[0] * (1.0f / DIM) + 1e-6f);
#pragma unroll
    for (int i = 0; i < 3; i++) {
        int d = t + i * 256;
        float dv = (i == 0 ? d0 : (i == 1 ? d1 : d2));
        float val = dv * rstd * g[d] + b[d];
        g_h[base + d] = val;
        float hi, lo;
        split_bf(val, hi, lo);
        g_hh[base + d] = __float2bfloat16_rn(hi);
        g_hl[base + d] = __float2bfloat16_rn(lo);
    }
}

// ---------------- layernorm over g_x (ln2 after wo) ----------------
__global__ void ln_kernel(const float* __restrict__ g, const float* __restrict__ b) {
    int row = blockIdx.x;
    int t = threadIdx.x;
    const float* xr = g_x + (size_t)row * DIM;
    float v0 = xr[t], v1 = xr[t + 256], v2 = xr[t + 512];
    __shared__ float red[256];
    red[t] = v0 + v1 + v2;
    __syncthreads();
    for (int o = 128; o > 0; o >>= 1) { if (t < o) red[t] += red[t + o]; __syncthreads(); }
    float mean = red[0] * (1.0f / DIM);
    __syncthreads();
    float d0 = v0 - mean, d1 = v1 - mean, d2 = v2 - mean;
    red[t] = d0 * d0 + d1 * d1 + d2 * d2;
    __syncthreads();
    for (int o = 128; o > 0; o >>= 1) { if (t < o) red[t] += red[t + o]; __syncthreads(); }
    float rstd = rsqrtf(red[0] * (1.0f / DIM) + 1e-6f);
    size_t base = (size_t)row * DIM;
#pragma unroll
    for (int i = 0; i < 3; i++) {
        int d = t + i * 256;
        float dv = (i == 0 ? d0 : (i == 1 ? d1 : d2));
        float val = dv * rstd * g[d] + b[d];
        g_h[base + d] = val;
        float hi, lo;
        split_bf(val, hi, lo);
        g_hh[base + d] = __float2bfloat16_rn(hi);
        g_hl[base + d] = __float2bfloat16_rn(lo);
    }
}

// ---------------- fused MoE scatter + next layernorm ----------------
// fp16mode: write fp16 hi/lo (for fp16 LM head) instead of bf16.
__global__ void scatter_ln_kernel(const float* __restrict__ g, const float* __restrict__ b,
                                  int fp16mode) {
    int row = blockIdx.x;
    int t = threadIdx.x;
    int r0 = g_perm[2 * row], r1 = g_perm[2 * row + 1];
    float w0 = g_roww[r0], w1 = g_roww[r1];
    size_t base = (size_t)row * DIM;
    const float* y0 = g_yff + (size_t)r0 * DIM;
    const float* y1 = g_yff + (size_t)r1 * DIM;
    float v[3];
#pragma unroll
    for (int i = 0; i < 3; i++) {
        int d = t + i * 256;
        v[i] = g_x[base + d] + w0 * y0[d] + w1 * y1[d];
        g_x[base + d] = v[i];
    }
    __shared__ float red[256];
    red[t] = v[0] + v[1] + v[2];
    __syncthreads();
    for (int o = 128; o > 0; o >>= 1) { if (t < o) red[t] += red[t + o]; __syncthreads(); }
    float mean = red[0] * (1.0f / DIM);
    __syncthreads();
    float d0 = v[0] - mean, d1 = v[1] - mean, d2 = v[2] - mean;
    red[t] = d0 * d0 + d1 * d1 + d2 * d2;
    __syncthreads();
    for (int o = 128; o > 0; o >>= 1) { if (t < o) red[t] += red[t + o]; __syncthreads(); }
    float rstd = rsqrtf(red[0] * (1.0f / DIM) + 1e-6f);
#pragma unroll
    for (int i = 0; i < 3; i++) {
        int d = t + i * 256;
        float dv = (i == 0 ? d0 : (i == 1 ? d1 : d2));
        float val = dv * rstd * g[d] + b[d];
        if (fp16mode) {
            __half hh = __float2half_rn(val);
            ((__half*)g_hh)[base + d] = hh;
            ((__half*)g_hl)[base + d] = __float2half_rn(val - __half2float(hh));
        } else {
            g_h[base + d] = val;
            float hi, lo;
            split_bf(val, hi, lo);
            g_hh[base + d] = __float2bfloat16_rn(hi);
            g_hl[base + d] = __float2bfloat16_rn(lo);
        }
    }
}

// ---------------- RoPE on q and k (in place) ----------------
__global__ void rope_kernel() {
    int idx = blockIdx.x * blockDim.x + threadIdx.x;
    if (idx >= TB * NH * 32) return;
    int j = idx & 31;
    int h = (idx >> 5) % NH;
    int t = idx / (32 * NH);
    int s = t % SEQ;
    float inv = exp2f(-(float)j * 0.41524101186092029f);
    float ang = (float)s * inv;
    float sn, cs;
    sincosf(ang, &sn, &cs);
    int base = t * DIM + h * HD;
    float a = g_q[base + j], b2 = g_q[base + 32 + j];
    g_q[base + j]      = a * cs - b2 * sn;
    g_q[base + 32 + j] = b2 * cs + a * sn;
    a = g_k[base + j]; b2 = g_k[base + 32 + j];
    g_k[base + j]      = a * cs - b2 * sn;
    g_k[base + 32 + j] = b2 * cs + a * sn;
}

// =====================================================================
//  flash attention (fp32, smem-tiled)
// =====================================================================
#define AQ 64
#define AKT 32
#define KVS 68
#define AQS_F (AQ * HD)
#define KVBUF_F (AKT * KVS)
#define KVSTG_F (2 * KVBUF_F)
#define ASMEM ((AQS_F + 2 * KVSTG_F) * 4)

__global__ void __launch_bounds__(256, 2) attn_kernel() {
    extern __shared__ float sm[];
    float* Qs = sm;
    float* KV = sm + AQS_F;
    const uint32_t kvu = smem_u32(KV);

    int tid = threadIdx.x, lane = tid & 31, w = tid >> 5;
    int qb = 15 - blockIdx.x;
    int bh = blockIdx.y;
    int b = bh / NH, h = bh % NH;
    int q0 = qb * AQ;
    size_t kvbase = ((size_t)b * SEQ) * DIM + h * HD;

    {
        const float* qsrc = g_q + ((size_t)(b * SEQ + q0)) * DIM + h * HD;
#pragma unroll
        for (int i = 0; i < 4; i++) {
            int e4 = tid + i * 256;
            int r = e4 >> 4, dq = (e4 & 15) * 4;
            float4 v = *(const float4*)(qsrc + (size_t)r * DIM + dq);
            v.x *= 0.125f; v.y *= 0.125f; v.z *= 0.125f; v.w *= 0.125f;
            *(float4*)(Qs + r * HD + dq) = v;
        }
    }

    const int nt = 2 * qb + 2;

    auto load_tile = [&](int t) {
        uint32_t dstb = kvu + (t & 1) * (KVSTG_F * 4);
#pragma unroll
        for (int i = 0; i < 2; i++) {
            int c = tid + i * 256;
            int r = c >> 4, of = (c & 15) * 4;
            size_t src = kvbase + (size_t)(t * AKT + r) * DIM + of;
            uint32_t d = dstb + (r * KVS + of) * 4;
            cpa16f(d, g_k + src);
            cpa16f(d + KVBUF_F * 4, g_v + src);
        }
        CP_COMMIT();
    };

    float m[8], l[8], a0[8], a1[8], sc[8];
#pragma unroll
    for (int q = 0; q < 8; q++) { m[q] = -1e30f; l[q] = 0.f; a0[q] = 0.f; a1[q] = 0.f; }

    const float* qsw = Qs + (w * 8) * HD;
    int qg0 = q0 + w * 8;

    load_tile(0);

    for (int t = 0; t < nt; t++) {
        if (t + 1 < nt) load_tile(t + 1); else CP_COMMIT();
        CP_WAIT1();
        __syncthreads();

        const float* Ksb = KV + (t & 1) * KVSTG_F;
        const float* Vsb = Ksb + KVBUF_F;

#pragma unroll
        for (int q = 0; q < 8; q++) sc[q] = 0.f;
#pragma unroll
        for (int dq = 0; dq < 16; dq++) {
            float4 kv = *(const float4*)(Ksb + lane * KVS + dq * 4);
#pragma unroll
            for (int q = 0; q < 8; q++) {
                float4 qv = *(const float4*)(qsw + q * HD + dq * 4);
                sc[q] += qv.x * kv.x + qv.y * kv.y + qv.z * kv.z + qv.w * kv.w;
            }
        }
        if (t >= nt - 2) {
            int kg = t * AKT + lane;
#pragma unroll
            for (int q = 0; q < 8; q++)
                if (kg > qg0 + q) sc[q] = -1e30f;
        }

#pragma unroll
        for (int q = 0; q < 8; q++) {
            float tm = sc[q];
#pragma unroll
            for (int o = 16; o; o >>= 1) tm = fmaxf(tm, __shfl_xor_sync(0xffffffffu, tm, o));
            float mn = fmaxf(m[q], tm);
            float corr = __expf(m[q] - mn);
            float p = __expf(sc[q] - mn);
            float ps = p;
#pragma unroll
            for (int o = 16; o; o >>= 1) ps += __shfl_xor_sync(0xffffffffu, ps, o);
            l[q] = l[q] * corr + ps;
            m[q] = mn;
            a0[q] *= corr;
            a1[q] *= corr;
            sc[q] = p;
        }

#pragma unroll
        for (int kk = 0; kk < AKT; kk++) {
            float v0 = Vsb[kk * KVS + lane];
            float v1 = Vsb[kk * KVS + lane + 32];
#pragma unroll
            for (int q = 0; q < 8; q++) {
                float pq = __shfl_sync(0xffffffffu, sc[q], kk);
                a0[q] += pq * v0;
                a1[q] += pq * v1;
            }
        }
        __syncthreads();
    }

#pragma unroll
    for (int q = 0; q < 8; q++) {
        float inv = 1.0f / l[q];
        float o0 = a0[q] * inv, o1 = a1[q] * inv;
        size_t ob = ((size_t)(b * SEQ + qg0 + q)) * DIM + h * HD;
        bf16 h0 = __float2bfloat16_rn(o0);
        bf16 h1 = __float2bfloat16_rn(o1);
        g_aoh[ob + lane] = h0;
        g_aol[ob + lane] = __float2bfloat16_rn(o0 - __bfloat162float(h0));
        g_aoh[ob + lane + 32] = h1;
        g_aol[ob + lane + 32] = __float2bfloat16_rn(o1 - __bfloat162float(h1));
    }
}

// ---------------- MoE gate logits (also zeroes counts) ------------------
__global__ void gate_kernel(const float* __restrict__ Wg) {
    int tok = blockIdx.x;
    int e = threadIdx.x >> 5;
    int lane = threadIdx.x & 31;
    if (tok == 0 && threadIdx.x < NE) g_counts[threadIdx.x] = 0;
    const float* hr = g_h + (size_t)tok * DIM;
    float s = 0.f;
    for (int d = lane; d < DIM; d += 32) s += hr[d] * Wg[d * NE + e];
#pragma unroll
    for (int o = 16; o; o >>= 1) s += __shfl_xor_sync(0xffffffffu, s, o);
    if (lane == 0) g_logits[tok * NE + e] = s;
}

__global__ void topk_kernel() {
    int t = blockIdx.x * blockDim.x + threadIdx.x;
    if (t >= TB) return;
    float lg[NE];
    float m = -1e30f;
#pragma unroll
    for (int e = 0; e < NE; e++) { lg[e] = g_logits[t * NE + e]; m = fmaxf(m, lg[e]); }
    float ssum = 0.f;
#pragma unroll
    for (int e = 0; e < NE; e++) { lg[e] = expf(lg[e] - m); ssum += lg[e]; }
    int i0 = 0;
#pragma unroll
    for (int e = 1; e < NE; e++) if (lg[e] > lg[i0]) i0 = e;
    int i1 = (i0 == 0) ? 1 : 0;
#pragma unroll
    for (int e = 0; e < NE; e++) if (e != i0 && e != i1 && lg[e] > lg[i1]) i1 = e;
    float v0 = lg[i0] / ssum, v1 = lg[i1] / ssum;
    float winv = 1.0f / (v0 + v1);
    g_te[2 * t] = i0; g_te[2 * t + 1] = i1;
    g_tw[2 * t] = v0 * winv; g_tw[2 * t + 1] = v1 * winv;
    atomicAdd(&g_counts[i0], 1);
    atomicAdd(&g_counts[i1], 1);
}

__global__ void scan_kernel() {
    int acc = 0;
    for (int e = 0; e < NE; e++) {
        g_offsets[e] = acc;
        acc += g_counts[e];
        g_cursor[e] = 0;
    }
}

__global__ void assign_kernel() {
    int t = blockIdx.x * blockDim.x + threadIdx.x;
    if (t >= TB) return;
    for (int kk = 0; kk < 2; kk++) {
        int e = g_te[2 * t + kk];
        int pos = g_offsets[e] + atomicAdd(&g_cursor[e], 1);
        g_rowtok[pos] = t;
        g_roww[pos] = g_tw[2 * t + kk];
        g_perm[2 * t + kk] = pos;
    }
}

// ---------------- host orchestration ----------------
extern "C" void kernel_launch(void* const* d_in, const int* in_sizes, int n_in,
                              void* d_out, int out_size) {
    (void)in_sizes; (void)n_in; (void)out_size;
    const int*   ids   = (const int*)  d_in[0];
    const float* emb   = (const float*)d_in[1];
    const float* ln1_g = (const float*)d_in[2];
    const float* ln1_b = (const float*)d_in[3];
    const float* ln2_g = (const float*)d_in[4];
    const float* ln2_b = (const float*)d_in[5];
    const float* Wq    = (const float*)d_in[6];
    const float* Wkv   = (const float*)d_in[7];
    const float* Wk    = (const float*)d_in[8];
    const float* Wv    = (const float*)d_in[9];
    const float* Wo    = (const float*)d_in[10];
    const float* Wg    = (const float*)d_in[11];
    const float* W1    = (const float*)d_in[12];
    const float* b1    = (const float*)d_in[13];
    const float* W2    = (const float*)d_in[14];
    const float* b2    = (const float*)d_in[15];
    const float* lnf_g = (const float*)d_in[16];
    const float* lnf_b = (const float*)d_in[17];
    const float* Wout  = (const float*)d_in[18];

    cudaFuncSetAttribute(qkv1_kernel,  cudaFuncAttributeMaxDynamicSharedMemorySize, GSMEM);
    cudaFuncSetAttribute(kv2_kernel,   cudaFuncAttributeMaxDynamicSharedMemorySize, GSMEM);
    cudaFuncSetAttribute(wo_kernel,    cudaFuncAttributeMaxDynamicSharedMemorySize, GSMEM);
    cudaFuncSetAttribute(moe1_kernel,  cudaFuncAttributeMaxDynamicSharedMemorySize, GSMEM);
    cudaFuncSetAttribute(moe2_kernel,  cudaFuncAttributeMaxDynamicSharedMemorySize, GSMEM);
    cudaFuncSetAttribute(lmhead_kernel, cudaFuncAttributeMaxDynamicSharedMemorySize, GSMEM16);
    cudaFuncSetAttribute(attn_kernel,  cudaFuncAttributeMaxDynamicSharedMemorySize, ASMEM);

    bf16 *wqh, *wql, *wkvh, *wkvl, *wkh, *wkl, *wvh, *wvl, *woh, *wol,
         *w1h, *w1l, *w2h, *w2l;
    __half* wouth;
    cudaGetSymbolAddress((void**)&wqh,  g_wqh);  cudaGetSymbolAddress((void**)&wql,  g_wql);
    cudaGetSymbolAddress((void**)&wkvh, g_wkvh); cudaGetSymbolAddress((void**)&wkvl, g_wkvl);
    cudaGetSymbolAddress((void**)&wkh,  g_wkh);  cudaGetSymbolAddress((void**)&wkl,  g_wkl);
    cudaGetSymbolAddress((void**)&wvh,  g_wvh);  cudaGetSymbolAddress((void**)&wvl,  g_wvl);
    cudaGetSymbolAddress((void**)&woh,  g_woh);  cudaGetSymbolAddress((void**)&wol,  g_wol);
    cudaGetSymbolAddress((void**)&w1h,  g_w1h);  cudaGetSymbolAddress((void**)&w1l,  g_w1l);
    cudaGetSymbolAddress((void**)&w2h,  g_w2h);  cudaGetSymbolAddress((void**)&w2l,  g_w2l);
    cudaGetSymbolAddress((void**)&wouth, g_wouth);

    auto wc = [&](const float* s, bf16* h, bf16* l, size_t n) {
        int n4 = (int)(n / 4);
        wconv_kernel<<<(n4 + 255) / 256, 256>>>(s, h, l, n4);
    };

    // Round-12 launch order (1-based #5 = qkv1, #6 = kv2 for ncu).
    embed_ln_kernel<<<TB, 256>>>(ids, emb, ln1_g, ln1_b);                     // 1
    wc(Wq, wqh, wql, (size_t)NLAYER * DIM * DIM);                             // 2
    {
        int n4 = NLAYER * DIM * DLAT / 4;                                     // 3
        wconv3_kernel<<<dim3((n4 + 255) / 256, 3), 256>>>(
            Wkv, wkvh, wkvl, Wk, wkh, wkl, Wv, wvh, wvl, n4);
    }
    wc(W1, w1h, w1l, (size_t)NLAYER * NE * DIM * DFF);                        // 4

    for (int l = 0; l < NLAYER; l++) {
        // --- attention block ---
        qkv1_kernel<<<dim3(15, TB / 128), 256, GSMEM>>>(l);                   // 5 (l==0)
        kv2_kernel<<<dim3(24, TB / 128), 256, GSMEM>>>(l);                    // 6 (l==0)
        rope_kernel<<<(TB * NH * 32 + 255) / 256, 256>>>();
        attn_kernel<<<dim3(SEQ / AQ, BATCH * NH), 256, ASMEM>>>();
        if (l == 0) {
            wc(Wo, woh, wol, (size_t)NLAYER * DIM * DIM);
            wc(W2, w2h, w2l, (size_t)NLAYER * NE * DFF * DIM);
            int n4o = DIM * NV / 4;
            wconvh_kernel<<<(n4o + 255) / 256, 256>>>(Wout, wouth, n4o);
        }
        wo_kernel<<<dim3(DIM / 64, TB / 128), 256, GSMEM>>>(l);

        // --- MoE block (round-12 structure) ---
        ln_kernel<<<TB, 256>>>(ln2_g + l * DIM, ln2_b + l * DIM);
        gate_kernel<<<TB, 256>>>(Wg + (size_t)l * DIM * NE);
        topk_kernel<<<TB / 256, 256>>>();
        scan_kernel<<<1, 1>>>();
        assign_kernel<<<TB / 256, 256>>>();
        moe1_kernel<<<dim3(DFF / 64, 2 * TB / 128, NE), 256, GSMEM>>>(b1, l);
        moe2_kernel<<<dim3(DIM / 64, 2 * TB / 128, NE), 256, GSMEM>>>(b2, l);

        // --- fused scatter + next LN (ln1 of next layer, or lnf) ---
        if (l + 1 < NLAYER)
            scatter_ln_kernel<<<TB, 256>>>(ln1_g + (l + 1) * DIM, ln1_b + (l + 1) * DIM, 0);
        else
            scatter_ln_kernel<<<TB, 256>>>(lnf_g, lnf_b, 1);   // fp16 hi/lo for LM head
    }

    // --- LM head (fp16 2-pass, round-12 grid orientation) ---
    lmhead_kernel<<<dim3(NV / 64, TB / 128), 256, GSMEM16>>>((float*)d_out);
}

// round 15
// speedup vs baseline: 1.6064x; 1.0456x over previous
#include <cuda_runtime.h>
#include <cuda_fp16.h>
#include <math.h>
#include <stdint.h>

// ---------------- problem dims ----------------
#define TB 2048
#define SEQ 1024
#define BATCH 2
#define DIM 768
#define NH 12
#define HD 64
#define DLAT 192
#define DFF 3072
#define NE 8
#define NV 32000
#define NLAYER 2

#define FLAG_ACC 1
#define FLAG_GELU 2

// ---------------- fp32 scratch ----------------
__device__ float g_x[TB * DIM];
__device__ float g_h[TB * DIM];
__device__ float g_q[TB * DIM];
__device__ float g_k[TB * DIM];
__device__ float g_v[TB * DIM];
__device__ float g_yff[2 * TB * DIM];
__device__ float g_logits[TB * NE];
__device__ float g_tw[TB * 2];
__device__ int   g_te[TB * 2];
__device__ int   g_counts[NE];
__device__ int   g_offsets[NE];
__device__ int   g_cursor[NE];
__device__ int   g_rowtok[2 * TB];
__device__ float g_roww[2 * TB];
__device__ int   g_perm[2 * TB];

// ---------------- fp16 hi/lo activations ----------------
__device__ __half g_hh[TB * DIM],  g_hl[TB * DIM];
__device__ __half g_lath[TB * DLAT], g_latl[TB * DLAT];
__device__ __half g_aoh[TB * DIM], g_aol[TB * DIM];
__device__ __half g_hffh[2 * TB * DFF], g_hffl[2 * TB * DFF];

// ---------------- fp16 weights (hi only; 2-pass scheme) ----------------
__device__ __half g_wqh[NLAYER * DIM * DIM];
__device__ __half g_wkvh[NLAYER * DIM * DLAT];
__device__ __half g_wkh[NLAYER * DLAT * DIM];
__device__ __half g_wvh[NLAYER * DLAT * DIM];
__device__ __half g_woh[NLAYER * DIM * DIM];
__device__ __half g_w1h[NLAYER * NE * DIM * DFF];
__device__ __half g_w2h[NLAYER * NE * DFF * DIM];
__device__ __half g_wouth[DIM * NV];

// ---------------- helpers ----------------
__device__ __forceinline__ uint32_t smem_u32(const void* p) {
    uint32_t a;
    asm("{ .reg .u64 t; cvta.to.shared.u64 t, %1; cvt.u32.u64 %0, t; }" : "=r"(a) : "l"(p));
    return a;
}
__device__ __forceinline__ float gelu_f(float x) {
    const float k0 = 0.7978845608028654f;
    float x3 = x * x * x;
    return 0.5f * x * (1.0f + tanhf(k0 * (x + 0.044715f * x3)));
}
__device__ __forceinline__ void mma16h(float d[4], const uint32_t a[4], const uint32_t b[2]) {
    asm volatile(
        "mma.sync.aligned.m16n8k16.row.col.f32.f16.f16.f32 "
        "{%0,%1,%2,%3},{%4,%5,%6,%7},{%8,%9},{%0,%1,%2,%3};"
        : "+f"(d[0]), "+f"(d[1]), "+f"(d[2]), "+f"(d[3])
        : "r"(a[0]), "r"(a[1]), "r"(a[2]), "r"(a[3]),
          "r"(b[0]), "r"(b[1]));
}
__device__ __forceinline__ void ldsm4(uint32_t r[4], uint32_t addr) {
    asm volatile("ldmatrix.sync.aligned.m8n8.x4.shared.b16 {%0,%1,%2,%3}, [%4];"
                 : "=r"(r[0]), "=r"(r[1]), "=r"(r[2]), "=r"(r[3]) : "r"(addr));
}
__device__ __forceinline__ void ldsm4t(uint32_t& r0, uint32_t& r1, uint32_t& r2,
                                       uint32_t& r3, uint32_t addr) {
    asm volatile("ldmatrix.sync.aligned.m8n8.x4.trans.shared.b16 {%0,%1,%2,%3}, [%4];"
                 : "=r"(r0), "=r"(r1), "=r"(r2), "=r"(r3) : "r"(addr));
}
__device__ __forceinline__ void cpa16(uint32_t dst, const void* src, int sz) {
    asm volatile("cp.async.cg.shared.global [%0], [%1], 16, %2;"
                 :: "r"(dst), "l"(src), "r"(sz) : "memory");
}
__device__ __forceinline__ void cpa16f(uint32_t dst, const void* src) {
    asm volatile("cp.async.cg.shared.global [%0], [%1], 16;"
                 :: "r"(dst), "l"(src) : "memory");
}
#define CP_COMMIT() asm volatile("cp.async.commit_group;" ::: "memory")
#define CP_WAIT1()  asm volatile("cp.async.wait_group 1;" ::: "memory")

// fp16 hi/lo store of a fp32 value
__device__ __forceinline__ void store_hf(__half* hp, __half* lp, size_t ix, float val) {
    __half hh = __float2half_rn(val);
    hp[ix] = hh;
    lp[ix] = __float2half_rn(val - __half2float(hh));
}

// ---------------- weight fp32 -> fp16 conversion ----------------
__device__ __forceinline__ void wconvh_body(const float* __restrict__ s,
                                            __half* __restrict__ h, int i, int n4) {
    if (i >= n4) return;
    float4 v = ((const float4*)s)[i];
    __half2 p0 = __floats2half2_rn(v.x, v.y);
    __half2 p1 = __floats2half2_rn(v.z, v.w);
    ((uint2*)h)[i] = make_uint2(*(uint32_t*)&p0, *(uint32_t*)&p1);
}
__global__ void wconvh_kernel(const float* __restrict__ s, __half* __restrict__ h, int n4) {
    wconvh_body(s, h, blockIdx.x * blockDim.x + threadIdx.x, n4);
}
__global__ void wconvh3_kernel(const float* __restrict__ s0, __half* __restrict__ h0,
                               const float* __restrict__ s1, __half* __restrict__ h1,
                               const float* __restrict__ s2, __half* __restrict__ h2,
                               int n4) {
    const float* s; __half* h;
    if (blockIdx.y == 0)      { s = s0; h = h0; }
    else if (blockIdx.y == 1) { s = s1; h = h1; }
    else                      { s = s2; h = h2; }
    wconvh_body(s, h, blockIdx.x * blockDim.x + threadIdx.x, n4);
}

// =====================================================================
//   fp16 2-pass mma.sync GEMM: D = (Ah + Al) @ B
//   cp.async 3-stage pipeline, ldmatrix(.trans), 128x64 tile, BK=32.
//   Stage: Ah 10240B | Al 10240B | B 4608B -> 25088B; 3 stages.
// =====================================================================
#define A_ROW_B 80
#define B_ROW_B 144
#define H_AL_B 10240
#define H_B_B 20480
#define H_STAGE_B 25088
#define NSTAGE 3
#define GS16 (H_STAGE_B * NSTAGE)

__device__ __forceinline__ void gemm16_tile(
    const __half* __restrict__ Ah, const __half* __restrict__ Al,
    const int* __restrict__ Aidx,
    const __half* __restrict__ B, const float* __restrict__ bias,
    float* __restrict__ C, __half* __restrict__ Chi, __half* __restrict__ Clo,
    int Mv, int N, int K, int m0, int n0, int flags)
{
    extern __shared__ uint32_t smu[];
    const uint32_t sb0 = smem_u32(smu);
    int tid = threadIdx.x, lane = tid & 31, warp = tid >> 5;
    int wm = (warp >> 1) * 32, wn = (warp & 1) * 32;

    int jA = tid & 3, rA = tid >> 2;
    int kB = tid >> 3, jB = tid & 7;
    int gmr0 = m0 + rA, gmr1 = m0 + rA + 64;
    int szA0 = gmr0 < Mv ? 16 : 0;
    int szA1 = gmr1 < Mv ? 16 : 0;
    int row0 = gmr0 < Mv ? (Aidx ? Aidx[gmr0] : gmr0) : 0;
    int row1 = gmr1 < Mv ? (Aidx ? Aidx[gmr1] : gmr1) : 0;
    const __half* pAh0 = Ah + (size_t)row0 * K + jA * 8;
    const __half* pAl0 = Al + (size_t)row0 * K + jA * 8;
    const __half* pAh1 = Ah + (size_t)row1 * K + jA * 8;
    const __half* pAl1 = Al + (size_t)row1 * K + jA * 8;
    const __half* pB = B + (size_t)kB * N + n0 + jB * 8;
    uint32_t dA0 = rA * A_ROW_B + jA * 16;
    uint32_t dA1 = dA0 + 64 * A_ROW_B;
    uint32_t dB  = kB * B_ROW_B + jB * 16;

    const int nk = K / 32;

    auto load_stage = [&](int c) {
        if (c < nk) {
            uint32_t st = sb0 + (c % NSTAGE) * H_STAGE_B;
            int kc = c * 32;
            cpa16(st + dA0, pAh0 + kc, szA0);
            cpa16(st + dA1, pAh1 + kc, szA1);
            cpa16(st + H_AL_B + dA0, pAl0 + kc, szA0);
            cpa16(st + H_AL_B + dA1, pAl1 + kc, szA1);
            cpa16f(st + H_B_B + dB, pB + (size_t)kc * N);
        }
        CP_COMMIT();
    };

    float acc[2][4][4] = {};

    load_stage(0);
    load_stage(1);

    uint32_t aAddr = (uint32_t)((wm + (lane & 15)) * A_ROW_B + ((lane >> 4) << 4));
    uint32_t bAddr = (uint32_t)(H_B_B + (lane & 15) * B_ROW_B
                                + (wn + ((lane >> 4) << 3)) * 2);

    for (int c = 0; c < nk; c++) {
        CP_WAIT1();
        __syncthreads();
        load_stage(c + 2);

        uint32_t st = sb0 + (c % NSTAGE) * H_STAGE_B;
#pragma unroll
        for (int ss = 0; ss < 2; ss++) {
            uint32_t ah[2][4], al[2][4], bh[4][2];
#pragma unroll
            for (int mt = 0; mt < 2; mt++) {
                uint32_t ao = st + aAddr + mt * 16 * A_ROW_B + ss * 32;
                ldsm4(ah[mt], ao);
                ldsm4(al[mt], ao + H_AL_B);
            }
#pragma unroll
            for (int ntp = 0; ntp < 2; ntp++) {
                uint32_t bo = st + bAddr + ss * 16 * B_ROW_B + ntp * 32;
                ldsm4t(bh[2 * ntp][0], bh[2 * ntp][1],
                       bh[2 * ntp + 1][0], bh[2 * ntp + 1][1], bo);
            }
#pragma unroll
            for (int mt = 0; mt < 2; mt++)
#pragma unroll
                for (int nt = 0; nt < 4; nt++) mma16h(acc[mt][nt], ah[mt], bh[nt]);
#pragma unroll
            for (int mt = 0; mt < 2; mt++)
#pragma unroll
                for (int nt = 0; nt < 4; nt++) mma16h(acc[mt][nt], al[mt], bh[nt]);
        }
    }

    int row = lane >> 2, cc = lane & 3;
#pragma unroll
    for (int mt = 0; mt < 2; mt++) {
#pragma unroll
        for (int h = 0; h < 2; h++) {
            int r = m0 + wm + mt * 16 + row + h * 8;
            if (r >= Mv) continue;
#pragma unroll
            for (int nt = 0; nt < 4; nt++) {
#pragma unroll
                for (int j = 0; j < 2; j++) {
                    int cn = n0 + wn + nt * 8 + cc * 2 + j;
                    float val = acc[mt][nt][h * 2 + j];
                    if (bias) val += bias[cn];
                    if (flags & FLAG_GELU) val = gelu_f(val);
                    size_t ix = (size_t)r * N + cn;
                    if (flags & FLAG_ACC) C[ix] += val;
                    else if (C) C[ix] = val;
                    if (Chi) store_hf(Chi, Clo, ix, val);
                }
            }
        }
    }
}

__global__ void __launch_bounds__(256, 2) qkv1_kernel(int l) {
    int bx = blockIdx.x;
    size_t wq = (size_t)l * DIM * DIM, wkv = (size_t)l * DIM * DLAT;
    if (bx < 12)
        gemm16_tile(g_hh, g_hl, nullptr, g_wqh + wq, nullptr,
                    g_q, nullptr, nullptr, TB, DIM, DIM, blockIdx.y * 128, bx * 64, 0);
    else
        gemm16_tile(g_hh, g_hl, nullptr, g_wkvh + wkv, nullptr,
                    nullptr, g_lath, g_latl, TB, DLAT, DIM,
                    blockIdx.y * 128, (bx - 12) * 64, 0);
}

__global__ void __launch_bounds__(256, 2) kv2_kernel(int l) {
    int bx = blockIdx.x;
    size_t w = (size_t)l * DLAT * DIM;
    if (bx < 12)
        gemm16_tile(g_lath, g_latl, nullptr, g_wkh + w, nullptr,
                    g_k, nullptr, nullptr, TB, DIM, DLAT, blockIdx.y * 128, bx * 64, 0);
    else
        gemm16_tile(g_lath, g_latl, nullptr, g_wvh + w, nullptr,
                    g_v, nullptr, nullptr, TB, DIM, DLAT,
                    blockIdx.y * 128, (bx - 12) * 64, 0);
}

__global__ void __launch_bounds__(256, 2) wo_kernel(int l) {
    size_t w = (size_t)l * DIM * DIM;
    gemm16_tile(g_aoh, g_aol, nullptr, g_woh + w, nullptr,
                g_x, nullptr, nullptr, TB, DIM, DIM,
                blockIdx.y * 128, blockIdx.x * 64, FLAG_ACC);
}

__global__ void __launch_bounds__(256, 2) moe1_kernel(const float* __restrict__ b1, int l) {
    int e = blockIdx.z;
    int cnt = g_counts[e];
    int m0 = blockIdx.y * 128;
    if (m0 >= cnt) return;
    int off = g_offsets[e];
    size_t w = ((size_t)l * NE + e) * DIM * DFF;
    gemm16_tile(g_hh, g_hl, g_rowtok + off, g_w1h + w,
                b1 + ((size_t)l * NE + e) * DFF,
                nullptr, g_hffh + (size_t)off * DFF, g_hffl + (size_t)off * DFF,
                cnt, DFF, DIM, m0, blockIdx.x * 64, FLAG_GELU);
}

__global__ void __launch_bounds__(256, 2) moe2_kernel(const float* __restrict__ b2, int l) {
    int e = blockIdx.z;
    int cnt = g_counts[e];
    int m0 = blockIdx.y * 128;
    if (m0 >= cnt) return;
    int off = g_offsets[e];
    size_t w = ((size_t)l * NE + e) * DFF * DIM;
    gemm16_tile(g_hffh + (size_t)off * DFF, g_hffl + (size_t)off * DFF, nullptr,
                g_w2h + w, b2 + ((size_t)l * NE + e) * DIM,
                g_yff + (size_t)off * DIM, nullptr, nullptr,
                cnt, DIM, DFF, m0, blockIdx.x * 64, 0);
}

__global__ void __launch_bounds__(256, 2) lmhead_kernel(float* __restrict__ out) {
    gemm16_tile(g_hh, g_hl, nullptr, g_wouth, nullptr,
                out, nullptr, nullptr, TB, NV, DIM,
                blockIdx.y * 128, blockIdx.x * 64, 0);
}

// ---------------- fused embed + ln1(layer0) ----------------
__global__ void embed_ln_kernel(const int* __restrict__ ids, const float* __restrict__ emb,
                                const float* __restrict__ g, const float* __restrict__ b) {
    int row = blockIdx.x;
    int t = threadIdx.x;
    const float* src = emb + (size_t)ids[row] * DIM;
    float v0 = src[t], v1 = src[t + 256], v2 = src[t + 512];
    size_t base = (size_t)row * DIM;
    g_x[base + t] = v0; g_x[base + t + 256] = v1; g_x[base + t + 512] = v2;
    __shared__ float red[256];
    red[t] = v0 + v1 + v2;
    __syncthreads();
    for (int o = 128; o > 0; o >>= 1) { if (t < o) red[t] += red[t + o]; __syncthreads(); }
    float mean = red[0] * (1.0f / DIM);
    __syncthreads();
    float d0 = v0 - mean, d1 = v1 - mean, d2 = v2 - mean;
    red[t] = d0 * d0 + d1 * d1 + d2 * d2;
    __syncthreads();
    for (int o = 128; o > 0; o >>= 1) { if (t < o) red[t] += red[t + o]; __syncthreads(); }
    float rstd = rsqrtf(red[0] * (1.0f / DIM) + 1e-6f);
#pragma unroll
    for (int i = 0; i < 3; i++) {
        int d = t + i * 256;
        float dv = (i == 0 ? d0 : (i == 1 ? d1 : d2));
        float val = dv * rstd * g[d] + b[d];
        g_h[base + d] = val;
        store_hf(g_hh, g_hl, base + d, val);
    }
}

// ---------------- layernorm over g_x (ln2 after wo) ----------------
__global__ void ln_kernel(const float* __restrict__ g, const float* __restrict__ b) {
    int row = blockIdx.x;
    int t = threadIdx.x;
    const float* xr = g_x + (size_t)row * DIM;
    float v0 = xr[t], v1 = xr[t + 256], v2 = xr[t + 512];
    __shared__ float red[256];
    red[t] = v0 + v1 + v2;
    __syncthreads();
    for (int o = 128; o > 0; o >>= 1) { if (t < o) red[t] += red[t + o]; __syncthreads(); }
    float mean = red[0] * (1.0f / DIM);
    __syncthreads();
    float d0 = v0 - mean, d1 = v1 - mean, d2 = v2 - mean;
    red[t] = d0 * d0 + d1 * d1 + d2 * d2;
    __syncthreads();
    for (int o = 128; o > 0; o >>= 1) { if (t < o) red[t] += red[t + o]; __syncthreads(); }
    float rstd = rsqrtf(red[0] * (1.0f / DIM) + 1e-6f);
    size_t base = (size_t)row * DIM;
#pragma unroll
    for (int i = 0; i < 3; i++) {
        int d = t + i * 256;
        float dv = (i == 0 ? d0 : (i == 1 ? d1 : d2));
        float val = dv * rstd * g[d] + b[d];
        g_h[base + d] = val;
        store_hf(g_hh, g_hl, base + d, val);
    }
}

// ---------------- fused MoE scatter + next layernorm ----------------
__global__ void scatter_ln_kernel(const float* __restrict__ g, const float* __restrict__ b) {
    int row = blockIdx.x;
    int t = threadIdx.x;
    int r0 = g_perm[2 * row], r1 = g_perm[2 * row + 1];
    float w0 = g_roww[r0], w1 = g_roww[r1];
    size_t base = (size_t)row * DIM;
    const float* y0 = g_yff + (size_t)r0 * DIM;
    const float* y1 = g_yff + (size_t)r1 * DIM;
    float v[3];
#pragma unroll
    for (int i = 0; i < 3; i++) {
        int d = t + i * 256;
        v[i] = g_x[base + d] + w0 * y0[d] + w1 * y1[d];
        g_x[base + d] = v[i];
    }
    __shared__ float red[256];
    red[t] = v[0] + v[1] + v[2];
    __syncthreads();
    for (int o = 128; o > 0; o >>= 1) { if (t < o) red[t] += red[t + o]; __syncthreads(); }
    float mean = red[0] * (1.0f / DIM);
    __syncthreads();
    float d0 = v[0] - mean, d1 = v[1] - mean, d2 = v[2] - mean;
    red[t] = d0 * d0 + d1 * d1 + d2 * d2;
    __syncthreads();
    for (int o = 128; o > 0; o >>= 1) { if (t < o) red[t] += red[t + o]; __syncthreads(); }
    float rstd = rsqrtf(red[0] * (1.0f / DIM) + 1e-6f);
#pragma unroll
    for (int i = 0; i < 3; i++) {
        int d = t + i * 256;
        float dv = (i == 0 ? d0 : (i == 1 ? d1 : d2));
        float val = dv * rstd * g[d] + b[d];
        g_h[base + d] = val;
        store_hf(g_hh, g_hl, base + d, val);
    }
}

// ---------------- RoPE on q and k (in place) ----------------
__global__ void rope_kernel() {
    int idx = blockIdx.x * blockDim.x + threadIdx.x;
    if (idx >= TB * NH * 32) return;
    int j = idx & 31;
    int h = (idx >> 5) % NH;
    int t = idx / (32 * NH);
    int s = t % SEQ;
    float inv = exp2f(-(float)j * 0.41524101186092029f);
    float ang = (float)s * inv;
    float sn, cs;
    sincosf(ang, &sn, &cs);
    int base = t * DIM + h * HD;
    float a = g_q[base + j], b2 = g_q[base + 32 + j];
    g_q[base + j]      = a * cs - b2 * sn;
    g_q[base + 32 + j] = b2 * cs + a * sn;
    a = g_k[base + j]; b2 = g_k[base + 32 + j];
    g_k[base + j]      = a * cs - b2 * sn;
    g_k[base + 32 + j] = b2 * cs + a * sn;
}

// =====================================================================
//  flash attention (fp32, smem-tiled); output fp16 hi/lo for Wo GEMM
// =====================================================================
#define AQ 64
#define AKT 32
#define KVS 68
#define AQS_F (AQ * HD)
#define KVBUF_F (AKT * KVS)
#define KVSTG_F (2 * KVBUF_F)
#define ASMEM ((AQS_F + 2 * KVSTG_F) * 4)

__global__ void __launch_bounds__(256, 2) attn_kernel() {
    extern __shared__ float sm[];
    float* Qs = sm;
    float* KV = sm + AQS_F;
    const uint32_t kvu = smem_u32(KV);

    int tid = threadIdx.x, lane = tid & 31, w = tid >> 5;
    int qb = 15 - blockIdx.x;
    int bh = blockIdx.y;
    int b = bh / NH, h = bh % NH;
    int q0 = qb * AQ;
    size_t kvbase = ((size_t)b * SEQ) * DIM + h * HD;

    {
        const float* qsrc = g_q + ((size_t)(b * SEQ + q0)) * DIM + h * HD;
#pragma unroll
        for (int i = 0; i < 4; i++) {
            int e4 = tid + i * 256;
            int r = e4 >> 4, dq = (e4 & 15) * 4;
            float4 v = *(const float4*)(qsrc + (size_t)r * DIM + dq);
            v.x *= 0.125f; v.y *= 0.125f; v.z *= 0.125f; v.w *= 0.125f;
            *(float4*)(Qs + r * HD + dq) = v;
        }
    }

    const int nt = 2 * qb + 2;

    auto load_tile = [&](int t) {
        uint32_t dstb = kvu + (t & 1) * (KVSTG_F * 4);
#pragma unroll
        for (int i = 0; i < 2; i++) {
            int c = tid + i * 256;
            int r = c >> 4, of = (c & 15) * 4;
            size_t src = kvbase + (size_t)(t * AKT + r) * DIM + of;
            uint32_t d = dstb + (r * KVS + of) * 4;
            cpa16f(d, g_k + src);
            cpa16f(d + KVBUF_F * 4, g_v + src);
        }
        CP_COMMIT();
    };

    float m[8], l[8], a0[8], a1[8], sc[8];
#pragma unroll
    for (int q = 0; q < 8; q++) { m[q] = -1e30f; l[q] = 0.f; a0[q] = 0.f; a1[q] = 0.f; }

    const float* qsw = Qs + (w * 8) * HD;
    int qg0 = q0 + w * 8;

    load_tile(0);

    for (int t = 0; t < nt; t++) {
        if (t + 1 < nt) load_tile(t + 1); else CP_COMMIT();
        CP_WAIT1();
        __syncthreads();

        const float* Ksb = KV + (t & 1) * KVSTG_F;
        const float* Vsb = Ksb + KVBUF_F;

#pragma unroll
        for (int q = 0; q < 8; q++) sc[q] = 0.f;
#pragma unroll
        for (int dq = 0; dq < 16; dq++) {
            float4 kv = *(const float4*)(Ksb + lane * KVS + dq * 4);
#pragma unroll
            for (int q = 0; q < 8; q++) {
                float4 qv = *(const float4*)(qsw + q * HD + dq * 4);
                sc[q] += qv.x * kv.x + qv.y * kv.y + qv.z * kv.z + qv.w * kv.w;
            }
        }
        if (t >= nt - 2) {
            int kg = t * AKT + lane;
#pragma unroll
            for (int q = 0; q < 8; q++)
                if (kg > qg0 + q) sc[q] = -1e30f;
        }

#pragma unroll
        for (int q = 0; q < 8; q++) {
            float tm = sc[q];
#pragma unroll
            for (int o = 16; o; o >>= 1) tm = fmaxf(tm, __shfl_xor_sync(0xffffffffu, tm, o));
            float mn = fmaxf(m[q], tm);
            float corr = __expf(m[q] - mn);
            float p = __expf(sc[q] - mn);
            float ps = p;
#pragma unroll
            for (int o = 16; o; o >>= 1) ps += __shfl_xor_sync(0xffffffffu, ps, o);
            l[q] = l[q] * corr + ps;
            m[q] = mn;
            a0[q] *= corr;
            a1[q] *= corr;
            sc[q] = p;
        }

#pragma unroll
        for (int kk = 0; kk < AKT; kk++) {
            float v0 = Vsb[kk * KVS + lane];
            float v1 = Vsb[kk * KVS + lane + 32];
#pragma unroll
            for (int q = 0; q < 8; q++) {
                float pq = __shfl_sync(0xffffffffu, sc[q], kk);
                a0[q] += pq * v0;
                a1[q] += pq * v1;
            }
        }
        __syncthreads();
    }

#pragma unroll
    for (int q = 0; q < 8; q++) {
        float inv = 1.0f / l[q];
        float o0 = a0[q] * inv, o1 = a1[q] * inv;
        size_t ob = ((size_t)(b * SEQ + qg0 + q)) * DIM + h * HD;
        store_hf(g_aoh, g_aol, ob + lane, o0);
        store_hf(g_aoh, g_aol, ob + lane + 32, o1);
    }
}

// ---------------- MoE gate logits (also zeroes counts) ------------------
__global__ void gate_kernel(const float* __restrict__ Wg) {
    int tok = blockIdx.x;
    int e = threadIdx.x >> 5;
    int lane = threadIdx.x & 31;
    if (tok == 0 && threadIdx.x < NE) g_counts[threadIdx.x] = 0;
    const float* hr = g_h + (size_t)tok * DIM;
    float s = 0.f;
    for (int d = lane; d < DIM; d += 32) s += hr[d] * Wg[d * NE + e];
#pragma unroll
    for (int o = 16; o; o >>= 1) s += __shfl_xor_sync(0xffffffffu, s, o);
    if (lane == 0) g_logits[tok * NE + e] = s;
}

__global__ void topk_kernel() {
    int t = blockIdx.x * blockDim.x + threadIdx.x;
    if (t >= TB) return;
    float lg[NE];
    float m = -1e30f;
#pragma unroll
    for (int e = 0; e < NE; e++) { lg[e] = g_logits[t * NE + e]; m = fmaxf(m, lg[e]); }
    float ssum = 0.f;
#pragma unroll
    for (int e = 0; e < NE; e++) { lg[e] = expf(lg[e] - m); ssum += lg[e]; }
    int i0 = 0;
#pragma unroll
    for (int e = 1; e < NE; e++) if (lg[e] > lg[i0]) i0 = e;
    int i1 = (i0 == 0) ? 1 : 0;
#pragma unroll
    for (int e = 0; e < NE; e++) if (e != i0 && e != i1 && lg[e] > lg[i1]) i1 = e;
    float v0 = lg[i0] / ssum, v1 = lg[i1] / ssum;
    float winv = 1.0f / (v0 + v1);
    g_te[2 * t] = i0; g_te[2 * t + 1] = i1;
    g_tw[2 * t] = v0 * winv; g_tw[2 * t + 1] = v1 * winv;
    atomicAdd(&g_counts[i0], 1);
    atomicAdd(&g_counts[i1], 1);
}

__global__ void scan_kernel() {
    int acc = 0;
    for (int e = 0; e < NE; e++) {
        g_offsets[e] = acc;
        acc += g_counts[e];
        g_cursor[e] = 0;
    }
}

__global__ void assign_kernel() {
    int t = blockIdx.x * blockDim.x + threadIdx.x;
    if (t >= TB) return;
    for (int kk = 0; kk < 2; kk++) {
        int e = g_te[2 * t + kk];
        int pos = g_offsets[e] + atomicAdd(&g_cursor[e], 1);
        g_rowtok[pos] = t;
        g_roww[pos] = g_tw[2 * t + kk];
        g_perm[2 * t + kk] = pos;
    }
}

// ---------------- host orchestration ----------------
extern "C" void kernel_launch(void* const* d_in, const int* in_sizes, int n_in,
                              void* d_out, int out_size) {
    (void)in_sizes; (void)n_in; (void)out_size;
    const int*   ids   = (const int*)  d_in[0];
    const float* emb   = (const float*)d_in[1];
    const float* ln1_g = (const float*)d_in[2];
    const float* ln1_b = (const float*)d_in[3];
    const float* ln2_g = (const float*)d_in[4];
    const float* ln2_b = (const float*)d_in[5];
    const float* Wq    = (const float*)d_in[6];
    const float* Wkv   = (const float*)d_in[7];
    const float* Wk    = (const float*)d_in[8];
    const float* Wv    = (const float*)d_in[9];
    const float* Wo    = (const float*)d_in[10];
    const float* Wg    = (const float*)d_in[11];
    const float* W1    = (const float*)d_in[12];
    const float* b1    = (const float*)d_in[13];
    const float* W2    = (const float*)d_in[14];
    const float* b2    = (const float*)d_in[15];
    const float* lnf_g = (const float*)d_in[16];
    const float* lnf_b = (const float*)d_in[17];
    const float* Wout  = (const float*)d_in[18];

    cudaFuncSetAttribute(qkv1_kernel,  cudaFuncAttributeMaxDynamicSharedMemorySize, GS16);
    cudaFuncSetAttribute(kv2_kernel,   cudaFuncAttributeMaxDynamicSharedMemorySize, GS16);
    cudaFuncSetAttribute(wo_kernel,    cudaFuncAttributeMaxDynamicSharedMemorySize, GS16);
    cudaFuncSetAttribute(moe1_kernel,  cudaFuncAttributeMaxDynamicSharedMemorySize, GS16);
    cudaFuncSetAttribute(moe2_kernel,  cudaFuncAttributeMaxDynamicSharedMemorySize, GS16);
    cudaFuncSetAttribute(lmhead_kernel, cudaFuncAttributeMaxDynamicSharedMemorySize, GS16);
    cudaFuncSetAttribute(attn_kernel,  cudaFuncAttributeMaxDynamicSharedMemorySize, ASMEM);

    __half *wqh, *wkvh, *wkh, *wvh, *woh, *w1h, *w2h, *wouth;
    cudaGetSymbolAddress((void**)&wqh,  g_wqh);
    cudaGetSymbolAddress((void**)&wkvh, g_wkvh);
    cudaGetSymbolAddress((void**)&wkh,  g_wkh);
    cudaGetSymbolAddress((void**)&wvh,  g_wvh);
    cudaGetSymbolAddress((void**)&woh,  g_woh);
    cudaGetSymbolAddress((void**)&w1h,  g_w1h);
    cudaGetSymbolAddress((void**)&w2h,  g_w2h);
    cudaGetSymbolAddress((void**)&wouth, g_wouth);

    auto wch = [&](const float* s, __half* h, size_t n) {
        int n4 = (int)(n / 4);
        wconvh_kernel<<<(n4 + 255) / 256, 256>>>(s, h, n4);
    };

    // Launch order: 1-based #4 = qkv1 so ncu captures a GEMM.
    embed_ln_kernel<<<TB, 256>>>(ids, emb, ln1_g, ln1_b);                     // 1
    wch(Wq, wqh, (size_t)NLAYER * DIM * DIM);                                 // 2
    {
        int n4 = NLAYER * DIM * DLAT / 4;                                     // 3
        wconvh3_kernel<<<dim3((n4 + 255) / 256, 3), 256>>>(
            Wkv, wkvh, Wk, wkh, Wv, wvh, n4);
    }

    for (int l = 0; l < NLAYER; l++) {
        // --- attention block ---
        qkv1_kernel<<<dim3(15, TB / 128), 256, GS16>>>(l);                    // 4 (l==0)
        kv2_kernel<<<dim3(24, TB / 128), 256, GS16>>>(l);
        rope_kernel<<<(TB * NH * 32 + 255) / 256, 256>>>();
        attn_kernel<<<dim3(SEQ / AQ, BATCH * NH), 256, ASMEM>>>();
        if (l == 0) {
            wch(Wo,   woh,  (size_t)NLAYER * DIM * DIM);
            wch(W1,   w1h,  (size_t)NLAYER * NE * DIM * DFF);
            wch(W2,   w2h,  (size_t)NLAYER * NE * DFF * DIM);
            wch(Wout, wouth, (size_t)DIM * NV);
        }
        wo_kernel<<<dim3(DIM / 64, TB / 128), 256, GS16>>>(l);

        // --- MoE block ---
        ln_kernel<<<TB, 256>>>(ln2_g + l * DIM, ln2_b + l * DIM);
        gate_kernel<<<TB, 256>>>(Wg + (size_t)l * DIM * NE);
        topk_kernel<<<TB / 256, 256>>>();
        scan_kernel<<<1, 1>>>();
        assign_kernel<<<TB / 256, 256>>>();
        moe1_kernel<<<dim3(DFF / 64, 2 * TB / 128, NE), 256, GS16>>>(b1, l);
        moe2_kernel<<<dim3(DIM / 64, 2 * TB / 128, NE), 256, GS16>>>(b2, l);

        // --- fused scatter + next LN (ln1 of next layer, or lnf) ---
        if (l + 1 < NLAYER)
            scatter_ln_kernel<<<TB, 256>>>(ln1_g + (l + 1) * DIM, ln1_b + (l + 1) * DIM);
        else
            scatter_ln_kernel<<<TB, 256>>>(lnf_g, lnf_b);
    }

    // --- LM head (fp16 2-pass) ---
    lmhead_kernel<<<dim3(NV / 64, TB / 128), 256, GS16>>>((float*)d_out);
}

// round 16
// speedup vs baseline: 1.6968x; 1.0563x over previous
#include <cuda_runtime.h>
#include <cuda_fp16.h>
#include <math.h>
#include <stdint.h>

// ---------------- problem dims ----------------
#define TB 2048
#define SEQ 1024
#define BATCH 2
#define DIM 768
#define NH 12
#define HD 64
#define DLAT 192
#define DFF 3072
#define NE 8
#define NV 32000
#define NLAYER 2

#define FLAG_ACC 1
#define FLAG_GELU 2

// ---------------- fp32 scratch ----------------
__device__ float g_x[TB * DIM];
__device__ float g_h[TB * DIM];
__device__ float g_q[TB * DIM];
__device__ float g_k[TB * DIM];
__device__ float g_v[TB * DIM];
__device__ float g_yff[2 * TB * DIM];
__device__ float g_logits[TB * NE];
__device__ float g_tw[TB * 2];
__device__ int   g_te[TB * 2];
__device__ int   g_counts[NE];
__device__ int   g_offsets[NE];
__device__ int   g_cursor[NE];
__device__ int   g_rowtok[2 * TB];
__device__ float g_roww[2 * TB];
__device__ int   g_perm[2 * TB];

// ---------------- fp16 hi/lo activations ----------------
__device__ __half g_hh[TB * DIM],  g_hl[TB * DIM];
__device__ __half g_lath[TB * DLAT], g_latl[TB * DLAT];
__device__ __half g_aoh[TB * DIM], g_aol[TB * DIM];
__device__ __half g_hffh[2 * TB * DFF], g_hffl[2 * TB * DFF];

// ---------------- fp16 weights (hi only; 2-pass scheme) ----------------
__device__ __half g_wqh[NLAYER * DIM * DIM];
__device__ __half g_wkvh[NLAYER * DIM * DLAT];
__device__ __half g_wkh[NLAYER * DLAT * DIM];
__device__ __half g_wvh[NLAYER * DLAT * DIM];
__device__ __half g_woh[NLAYER * DIM * DIM];
__device__ __half g_w1h[NLAYER * NE * DIM * DFF];
__device__ __half g_w2h[NLAYER * NE * DFF * DIM];
__device__ __half g_wouth[DIM * NV];

// ---------------- helpers ----------------
__device__ __forceinline__ uint32_t smem_u32(const void* p) {
    uint32_t a;
    asm("{ .reg .u64 t; cvta.to.shared.u64 t, %1; cvt.u32.u64 %0, t; }" : "=r"(a) : "l"(p));
    return a;
}
__device__ __forceinline__ float gelu_f(float x) {
    const float k0 = 0.7978845608028654f;
    float x3 = x * x * x;
    return 0.5f * x * (1.0f + tanhf(k0 * (x + 0.044715f * x3)));
}
__device__ __forceinline__ void mma16h(float d[4], const uint32_t a[4], const uint32_t b[2]) {
    asm volatile(
        "mma.sync.aligned.m16n8k16.row.col.f32.f16.f16.f32 "
        "{%0,%1,%2,%3},{%4,%5,%6,%7},{%8,%9},{%0,%1,%2,%3};"
        : "+f"(d[0]), "+f"(d[1]), "+f"(d[2]), "+f"(d[3])
        : "r"(a[0]), "r"(a[1]), "r"(a[2]), "r"(a[3]),
          "r"(b[0]), "r"(b[1]));
}
__device__ __forceinline__ void ldsm4(uint32_t r[4], uint32_t addr) {
    asm volatile("ldmatrix.sync.aligned.m8n8.x4.shared.b16 {%0,%1,%2,%3}, [%4];"
                 : "=r"(r[0]), "=r"(r[1]), "=r"(r[2]), "=r"(r[3]) : "r"(addr));
}
__device__ __forceinline__ void ldsm4t(uint32_t& r0, uint32_t& r1, uint32_t& r2,
                                       uint32_t& r3, uint32_t addr) {
    asm volatile("ldmatrix.sync.aligned.m8n8.x4.trans.shared.b16 {%0,%1,%2,%3}, [%4];"
                 : "=r"(r0), "=r"(r1), "=r"(r2), "=r"(r3) : "r"(addr));
}
__device__ __forceinline__ void cpa16(uint32_t dst, const void* src, int sz) {
    asm volatile("cp.async.cg.shared.global [%0], [%1], 16, %2;"
                 :: "r"(dst), "l"(src), "r"(sz) : "memory");
}
__device__ __forceinline__ void cpa16f(uint32_t dst, const void* src) {
    asm volatile("cp.async.cg.shared.global [%0], [%1], 16;"
                 :: "r"(dst), "l"(src) : "memory");
}
#define CP_COMMIT() asm volatile("cp.async.commit_group;" ::: "memory")
#define CP_WAIT1()  asm volatile("cp.async.wait_group 1;" ::: "memory")

// fp16 hi/lo store of a fp32 value
__device__ __forceinline__ void store_hf(__half* hp, __half* lp, size_t ix, float val) {
    __half hh = __float2half_rn(val);
    hp[ix] = hh;
    lp[ix] = __float2half_rn(val - __half2float(hh));
}

// ---------------- weight fp32 -> fp16 conversion ----------------
__device__ __forceinline__ void wconvh_body(const float* __restrict__ s,
                                            __half* __restrict__ h, int i, int n4) {
    if (i >= n4) return;
    float4 v = ((const float4*)s)[i];
    __half2 p0 = __floats2half2_rn(v.x, v.y);
    __half2 p1 = __floats2half2_rn(v.z, v.w);
    ((uint2*)h)[i] = make_uint2(*(uint32_t*)&p0, *(uint32_t*)&p1);
}
__global__ void wconvh_kernel(const float* __restrict__ s, __half* __restrict__ h, int n4) {
    wconvh_body(s, h, blockIdx.x * blockDim.x + threadIdx.x, n4);
}
__global__ void wconvh3_kernel(const float* __restrict__ s0, __half* __restrict__ h0,
                               const float* __restrict__ s1, __half* __restrict__ h1,
                               const float* __restrict__ s2, __half* __restrict__ h2,
                               int n4) {
    const float* s; __half* h;
    if (blockIdx.y == 0)      { s = s0; h = h0; }
    else if (blockIdx.y == 1) { s = s1; h = h1; }
    else                      { s = s2; h = h2; }
    wconvh_body(s, h, blockIdx.x * blockDim.x + threadIdx.x, n4);
}

// =====================================================================
//   fp16 2-pass mma.sync GEMM: D = (Ah + Al) @ B
//   cp.async 3-stage pipeline, ldmatrix(.trans), 128x64 tile, BK=32.
//   Stage: Ah 10240B | Al 10240B | B 4608B -> 25088B; 3 stages.
//   3 CTAs/SM (85 regs cap, 220.5KB smem of 228KB).
// =====================================================================
#define A_ROW_B 80
#define B_ROW_B 144
#define H_AL_B 10240
#define H_B_B 20480
#define H_STAGE_B 25088
#define NSTAGE 3
#define GS16 (H_STAGE_B * NSTAGE)

__device__ __forceinline__ void gemm16_tile(
    const __half* __restrict__ Ah, const __half* __restrict__ Al,
    const int* __restrict__ Aidx,
    const __half* __restrict__ B, const float* __restrict__ bias,
    float* __restrict__ C, __half* __restrict__ Chi, __half* __restrict__ Clo,
    int Mv, int N, int K, int m0, int n0, int flags)
{
    extern __shared__ uint32_t smu[];
    const uint32_t sb0 = smem_u32(smu);
    int tid = threadIdx.x, lane = tid & 31, warp = tid >> 5;
    int wm = (warp >> 1) * 32, wn = (warp & 1) * 32;

    int jA = tid & 3, rA = tid >> 2;
    int kB = tid >> 3, jB = tid & 7;
    int gmr0 = m0 + rA, gmr1 = m0 + rA + 64;
    int szA0 = gmr0 < Mv ? 16 : 0;
    int szA1 = gmr1 < Mv ? 16 : 0;
    int row0 = gmr0 < Mv ? (Aidx ? Aidx[gmr0] : gmr0) : 0;
    int row1 = gmr1 < Mv ? (Aidx ? Aidx[gmr1] : gmr1) : 0;
    const __half* pAh0 = Ah + (size_t)row0 * K + jA * 8;
    const __half* pAl0 = Al + (size_t)row0 * K + jA * 8;
    const __half* pAh1 = Ah + (size_t)row1 * K + jA * 8;
    const __half* pAl1 = Al + (size_t)row1 * K + jA * 8;
    const __half* pB = B + (size_t)kB * N + n0 + jB * 8;
    uint32_t dA0 = rA * A_ROW_B + jA * 16;
    uint32_t dA1 = dA0 + 64 * A_ROW_B;
    uint32_t dB  = kB * B_ROW_B + jB * 16;

    const int nk = K / 32;

    auto load_stage = [&](int c) {
        if (c < nk) {
            uint32_t st = sb0 + (c % NSTAGE) * H_STAGE_B;
            int kc = c * 32;
            cpa16(st + dA0, pAh0 + kc, szA0);
            cpa16(st + dA1, pAh1 + kc, szA1);
            cpa16(st + H_AL_B + dA0, pAl0 + kc, szA0);
            cpa16(st + H_AL_B + dA1, pAl1 + kc, szA1);
            cpa16f(st + H_B_B + dB, pB + (size_t)kc * N);
        }
        CP_COMMIT();
    };

    float acc[2][4][4] = {};

    load_stage(0);
    load_stage(1);

    uint32_t aAddr = (uint32_t)((wm + (lane & 15)) * A_ROW_B + ((lane >> 4) << 4));
    uint32_t bAddr = (uint32_t)(H_B_B + (lane & 15) * B_ROW_B
                                + (wn + ((lane >> 4) << 3)) * 2);

    for (int c = 0; c < nk; c++) {
        CP_WAIT1();
        __syncthreads();
        load_stage(c + 2);

        uint32_t st = sb0 + (c % NSTAGE) * H_STAGE_B;
#pragma unroll
        for (int ss = 0; ss < 2; ss++) {
            uint32_t ah[2][4], al[2][4], bh[4][2];
#pragma unroll
            for (int mt = 0; mt < 2; mt++) {
                uint32_t ao = st + aAddr + mt * 16 * A_ROW_B + ss * 32;
                ldsm4(ah[mt], ao);
                ldsm4(al[mt], ao + H_AL_B);
            }
#pragma unroll
            for (int ntp = 0; ntp < 2; ntp++) {
                uint32_t bo = st + bAddr + ss * 16 * B_ROW_B + ntp * 32;
                ldsm4t(bh[2 * ntp][0], bh[2 * ntp][1],
                       bh[2 * ntp + 1][0], bh[2 * ntp + 1][1], bo);
            }
#pragma unroll
            for (int mt = 0; mt < 2; mt++)
#pragma unroll
                for (int nt = 0; nt < 4; nt++) mma16h(acc[mt][nt], ah[mt], bh[nt]);
#pragma unroll
            for (int mt = 0; mt < 2; mt++)
#pragma unroll
                for (int nt = 0; nt < 4; nt++) mma16h(acc[mt][nt], al[mt], bh[nt]);
        }
    }

    int row = lane >> 2, cc = lane & 3;
#pragma unroll
    for (int mt = 0; mt < 2; mt++) {
#pragma unroll
        for (int h = 0; h < 2; h++) {
            int r = m0 + wm + mt * 16 + row + h * 8;
            if (r >= Mv) continue;
#pragma unroll
            for (int nt = 0; nt < 4; nt++) {
#pragma unroll
                for (int j = 0; j < 2; j++) {
                    int cn = n0 + wn + nt * 8 + cc * 2 + j;
                    float val = acc[mt][nt][h * 2 + j];
                    if (bias) val += bias[cn];
                    if (flags & FLAG_GELU) val = gelu_f(val);
                    size_t ix = (size_t)r * N + cn;
                    if (flags & FLAG_ACC) C[ix] += val;
                    else if (C) C[ix] = val;
                    if (Chi) store_hf(Chi, Clo, ix, val);
                }
            }
        }
    }
}

__global__ void __launch_bounds__(256, 3) qkv1_kernel(int l) {
    int bx = blockIdx.x;
    size_t wq = (size_t)l * DIM * DIM, wkv = (size_t)l * DIM * DLAT;
    if (bx < 12)
        gemm16_tile(g_hh, g_hl, nullptr, g_wqh + wq, nullptr,
                    g_q, nullptr, nullptr, TB, DIM, DIM, blockIdx.y * 128, bx * 64, 0);
    else
        gemm16_tile(g_hh, g_hl, nullptr, g_wkvh + wkv, nullptr,
                    nullptr, g_lath, g_latl, TB, DLAT, DIM,
                    blockIdx.y * 128, (bx - 12) * 64, 0);
}

__global__ void __launch_bounds__(256, 3) kv2_kernel(int l) {
    int bx = blockIdx.x;
    size_t w = (size_t)l * DLAT * DIM;
    if (bx < 12)
        gemm16_tile(g_lath, g_latl, nullptr, g_wkh + w, nullptr,
                    g_k, nullptr, nullptr, TB, DIM, DLAT, blockIdx.y * 128, bx * 64, 0);
    else
        gemm16_tile(g_lath, g_latl, nullptr, g_wvh + w, nullptr,
                    g_v, nullptr, nullptr, TB, DIM, DLAT,
                    blockIdx.y * 128, (bx - 12) * 64, 0);
}

__global__ void __launch_bounds__(256, 3) wo_kernel(int l) {
    size_t w = (size_t)l * DIM * DIM;
    gemm16_tile(g_aoh, g_aol, nullptr, g_woh + w, nullptr,
                g_x, nullptr, nullptr, TB, DIM, DIM,
                blockIdx.y * 128, blockIdx.x * 64, FLAG_ACC);
}

__global__ void __launch_bounds__(256, 3) moe1_kernel(const float* __restrict__ b1, int l) {
    int e = blockIdx.z;
    int cnt = g_counts[e];
    int m0 = blockIdx.y * 128;
    if (m0 >= cnt) return;
    int off = g_offsets[e];
    size_t w = ((size_t)l * NE + e) * DIM * DFF;
    gemm16_tile(g_hh, g_hl, g_rowtok + off, g_w1h + w,
                b1 + ((size_t)l * NE + e) * DFF,
                nullptr, g_hffh + (size_t)off * DFF, g_hffl + (size_t)off * DFF,
                cnt, DFF, DIM, m0, blockIdx.x * 64, FLAG_GELU);
}

__global__ void __launch_bounds__(256, 3) moe2_kernel(const float* __restrict__ b2, int l) {
    int e = blockIdx.z;
    int cnt = g_counts[e];
    int m0 = blockIdx.y * 128;
    if (m0 >= cnt) return;
    int off = g_offsets[e];
    size_t w = ((size_t)l * NE + e) * DFF * DIM;
    gemm16_tile(g_hffh + (size_t)off * DFF, g_hffl + (size_t)off * DFF, nullptr,
                g_w2h + w, b2 + ((size_t)l * NE + e) * DIM,
                g_yff + (size_t)off * DIM, nullptr, nullptr,
                cnt, DIM, DFF, m0, blockIdx.x * 64, 0);
}

__global__ void __launch_bounds__(256, 3) lmhead_kernel(float* __restrict__ out) {
    gemm16_tile(g_hh, g_hl, nullptr, g_wouth, nullptr,
                out, nullptr, nullptr, TB, NV, DIM,
                blockIdx.y * 128, blockIdx.x * 64, 0);
}

// ---------------- fused embed + ln1(layer0) ----------------
__global__ void embed_ln_kernel(const int* __restrict__ ids, const float* __restrict__ emb,
                                const float* __restrict__ g, const float* __restrict__ b) {
    int row = blockIdx.x;
    int t = threadIdx.x;
    const float* src = emb + (size_t)ids[row] * DIM;
    float v0 = src[t], v1 = src[t + 256], v2 = src[t + 512];
    size_t base = (size_t)row * DIM;
    g_x[base + t] = v0; g_x[base + t + 256] = v1; g_x[base + t + 512] = v2;
    __shared__ float red[256];
    red[t] = v0 + v1 + v2;
    __syncthreads();
    for (int o = 128; o > 0; o >>= 1) { if (t < o) red[t] += red[t + o]; __syncthreads(); }
    float mean = red[0] * (1.0f / DIM);
    __syncthreads();
    float d0 = v0 - mean, d1 = v1 - mean, d2 = v2 - mean;
    red[t] = d0 * d0 + d1 * d1 + d2 * d2;
    __syncthreads();
    for (int o = 128; o > 0; o >>= 1) { if (t < o) red[t] += red[t + o]; __syncthreads(); }
    float rstd = rsqrtf(red[0] * (1.0f / DIM) + 1e-6f);
#pragma unroll
    for (int i = 0; i < 3; i++) {
        int d = t + i * 256;
        float dv = (i == 0 ? d0 : (i == 1 ? d1 : d2));
        float val = dv * rstd * g[d] + b[d];
        g_h[base + d] = val;
        store_hf(g_hh, g_hl, base + d, val);
    }
}

// ---------------- layernorm over g_x (ln2 after wo) ----------------
__global__ void ln_kernel(const float* __restrict__ g, const float* __restrict__ b) {
    int row = blockIdx.x;
    int t = threadIdx.x;
    const float* xr = g_x + (size_t)row * DIM;
    float v0 = xr[t], v1 = xr[t + 256], v2 = xr[t + 512];
    __shared__ float red[256];
    red[t] = v0 + v1 + v2;
    __syncthreads();
    for (int o = 128; o > 0; o >>= 1) { if (t < o) red[t] += red[t + o]; __syncthreads(); }
    float mean = red[0] * (1.0f / DIM);
    __syncthreads();
    float d0 = v0 - mean, d1 = v1 - mean, d2 = v2 - mean;
    red[t] = d0 * d0 + d1 * d1 + d2 * d2;
    __syncthreads();
    for (int o = 128; o > 0; o >>= 1) { if (t < o) red[t] += red[t + o]; __syncthreads(); }
    float rstd = rsqrtf(red[0] * (1.0f / DIM) + 1e-6f);
    size_t base = (size_t)row * DIM;
#pragma unroll
    for (int i = 0; i < 3; i++) {
        int d = t + i * 256;
        float dv = (i == 0 ? d0 : (i == 1 ? d1 : d2));
        float val = dv * rstd * g[d] + b[d];
        g_h[base + d] = val;
        store_hf(g_hh, g_hl, base + d, val);
    }
}

// ---------------- fused MoE scatter + next layernorm ----------------
__global__ void scatter_ln_kernel(const float* __restrict__ g, const float* __restrict__ b) {
    int row = blockIdx.x;
    int t = threadIdx.x;
    int r0 = g_perm[2 * row], r1 = g_perm[2 * row + 1];
    float w0 = g_roww[r0], w1 = g_roww[r1];
    size_t base = (size_t)row * DIM;
    const float* y0 = g_yff + (size_t)r0 * DIM;
    const float* y1 = g_yff + (size_t)r1 * DIM;
    float v[3];
#pragma unroll
    for (int i = 0; i < 3; i++) {
        int d = t + i * 256;
        v[i] = g_x[base + d] + w0 * y0[d] + w1 * y1[d];
        g_x[base + d] = v[i];
    }
    __shared__ float red[256];
    red[t] = v[0] + v[1] + v[2];
    __syncthreads();
    for (int o = 128; o > 0; o >>= 1) { if (t < o) red[t] += red[t + o]; __syncthreads(); }
    float mean = red[0] * (1.0f / DIM);
    __syncthreads();
    float d0 = v[0] - mean, d1 = v[1] - mean, d2 = v[2] - mean;
    red[t] = d0 * d0 + d1 * d1 + d2 * d2;
    __syncthreads();
    for (int o = 128; o > 0; o >>= 1) { if (t < o) red[t] += red[t + o]; __syncthreads(); }
    float rstd = rsqrtf(red[0] * (1.0f / DIM) + 1e-6f);
#pragma unroll
    for (int i = 0; i < 3; i++) {
        int d = t + i * 256;
        float dv = (i == 0 ? d0 : (i == 1 ? d1 : d2));
        float val = dv * rstd * g[d] + b[d];
        g_h[base + d] = val;
        store_hf(g_hh, g_hl, base + d, val);
    }
}

// ---------------- RoPE on q and k (in place) ----------------
__global__ void rope_kernel() {
    int idx = blockIdx.x * blockDim.x + threadIdx.x;
    if (idx >= TB * NH * 32) return;
    int j = idx & 31;
    int h = (idx >> 5) % NH;
    int t = idx / (32 * NH);
    int s = t % SEQ;
    float inv = exp2f(-(float)j * 0.41524101186092029f);
    float ang = (float)s * inv;
    float sn, cs;
    sincosf(ang, &sn, &cs);
    int base = t * DIM + h * HD;
    float a = g_q[base + j], b2 = g_q[base + 32 + j];
    g_q[base + j]      = a * cs - b2 * sn;
    g_q[base + 32 + j] = b2 * cs + a * sn;
    a = g_k[base + j]; b2 = g_k[base + 32 + j];
    g_k[base + j]      = a * cs - b2 * sn;
    g_k[base + 32 + j] = b2 * cs + a * sn;
}

// =====================================================================
//  flash attention (fp32, smem-tiled); output fp16 hi/lo for Wo GEMM
// =====================================================================
#define AQ 64
#define AKT 32
#define KVS 68
#define AQS_F (AQ * HD)
#define KVBUF_F (AKT * KVS)
#define KVSTG_F (2 * KVBUF_F)
#define ASMEM ((AQS_F + 2 * KVSTG_F) * 4)

__global__ void __launch_bounds__(256, 2) attn_kernel() {
    extern __shared__ float sm[];
    float* Qs = sm;
    float* KV = sm + AQS_F;
    const uint32_t kvu = smem_u32(KV);

    int tid = threadIdx.x, lane = tid & 31, w = tid >> 5;
    int qb = 15 - blockIdx.x;
    int bh = blockIdx.y;
    int b = bh / NH, h = bh % NH;
    int q0 = qb * AQ;
    size_t kvbase = ((size_t)b * SEQ) * DIM + h * HD;

    {
        const float* qsrc = g_q + ((size_t)(b * SEQ + q0)) * DIM + h * HD;
#pragma unroll
        for (int i = 0; i < 4; i++) {
            int e4 = tid + i * 256;
            int r = e4 >> 4, dq = (e4 & 15) * 4;
            float4 v = *(const float4*)(qsrc + (size_t)r * DIM + dq);
            v.x *= 0.125f; v.y *= 0.125f; v.z *= 0.125f; v.w *= 0.125f;
            *(float4*)(Qs + r * HD + dq) = v;
        }
    }

    const int nt = 2 * qb + 2;

    auto load_tile = [&](int t) {
        uint32_t dstb = kvu + (t & 1) * (KVSTG_F * 4);
#pragma unroll
        for (int i = 0; i < 2; i++) {
            int c = tid + i * 256;
            int r = c >> 4, of = (c & 15) * 4;
            size_t src = kvbase + (size_t)(t * AKT + r) * DIM + of;
            uint32_t d = dstb + (r * KVS + of) * 4;
            cpa16f(d, g_k + src);
            cpa16f(d + KVBUF_F * 4, g_v + src);
        }
        CP_COMMIT();
    };

    float m[8], l[8], a0[8], a1[8], sc[8];
#pragma unroll
    for (int q = 0; q < 8; q++) { m[q] = -1e30f; l[q] = 0.f; a0[q] = 0.f; a1[q] = 0.f; }

    const float* qsw = Qs + (w * 8) * HD;
    int qg0 = q0 + w * 8;

    load_tile(0);

    for (int t = 0; t < nt; t++) {
        if (t + 1 < nt) load_tile(t + 1); else CP_COMMIT();
        CP_WAIT1();
        __syncthreads();

        const float* Ksb = KV + (t & 1) * KVSTG_F;
        const float* Vsb = Ksb + KVBUF_F;

#pragma unroll
        for (int q = 0; q < 8; q++) sc[q] = 0.f;
#pragma unroll
        for (int dq = 0; dq < 16; dq++) {
            float4 kv = *(const float4*)(Ksb + lane * KVS + dq * 4);
#pragma unroll
            for (int q = 0; q < 8; q++) {
                float4 qv = *(const float4*)(qsw + q * HD + dq * 4);
                sc[q] += qv.x * kv.x + qv.y * kv.y + qv.z * kv.z + qv.w * kv.w;
            }
        }
        if (t >= nt - 2) {
            int kg = t * AKT + lane;
#pragma unroll
            for (int q = 0; q < 8; q++)
                if (kg > qg0 + q) sc[q] = -1e30f;
        }

#pragma unroll
        for (int q = 0; q < 8; q++) {
            float tm = sc[q];
#pragma unroll
            for (int o = 16; o; o >>= 1) tm = fmaxf(tm, __shfl_xor_sync(0xffffffffu, tm, o));
            float mn = fmaxf(m[q], tm);
            float corr = __expf(m[q] - mn);
            float p = __expf(sc[q] - mn);
            float ps = p;
#pragma unroll
            for (int o = 16; o; o >>= 1) ps += __shfl_xor_sync(0xffffffffu, ps, o);
            l[q] = l[q] * corr + ps;
            m[q] = mn;
            a0[q] *= corr;
            a1[q] *= corr;
            sc[q] = p;
        }

#pragma unroll
        for (int kk = 0; kk < AKT; kk++) {
            float v0 = Vsb[kk * KVS + lane];
            float v1 = Vsb[kk * KVS + lane + 32];
#pragma unroll
            for (int q = 0; q < 8; q++) {
                float pq = __shfl_sync(0xffffffffu, sc[q], kk);
                a0[q] += pq * v0;
                a1[q] += pq * v1;
            }
        }
        __syncthreads();
    }

#pragma unroll
    for (int q = 0; q < 8; q++) {
        float inv = 1.0f / l[q];
        float o0 = a0[q] * inv, o1 = a1[q] * inv;
        size_t ob = ((size_t)(b * SEQ + qg0 + q)) * DIM + h * HD;
        store_hf(g_aoh, g_aol, ob + lane, o0);
        store_hf(g_aoh, g_aol, ob + lane + 32, o1);
    }
}

// ---------------- MoE gate logits (also zeroes counts) ------------------
__global__ void gate_kernel(const float* __restrict__ Wg) {
    int tok = blockIdx.x;
    int e = threadIdx.x >> 5;
    int lane = threadIdx.x & 31;
    if (tok == 0 && threadIdx.x < NE) g_counts[threadIdx.x] = 0;
    const float* hr = g_h + (size_t)tok * DIM;
    float s = 0.f;
    for (int d = lane; d < DIM; d += 32) s += hr[d] * Wg[d * NE + e];
#pragma unroll
    for (int o = 16; o; o >>= 1) s += __shfl_xor_sync(0xffffffffu, s, o);
    if (lane == 0) g_logits[tok * NE + e] = s;
}

__global__ void topk_kernel() {
    int t = blockIdx.x * blockDim.x + threadIdx.x;
    if (t >= TB) return;
    float lg[NE];
    float m = -1e30f;
#pragma unroll
    for (int e = 0; e < NE; e++) { lg[e] = g_logits[t * NE + e]; m = fmaxf(m, lg[e]); }
    float ssum = 0.f;
#pragma unroll
    for (int e = 0; e < NE; e++) { lg[e] = expf(lg[e] - m); ssum += lg[e]; }
    int i0 = 0;
#pragma unroll
    for (int e = 1; e < NE; e++) if (lg[e] > lg[i0]) i0 = e;
    int i1 = (i0 == 0) ? 1 : 0;
#pragma unroll
    for (int e = 0; e < NE; e++) if (e != i0 && e != i1 && lg[e] > lg[i1]) i1 = e;
    float v0 = lg[i0] / ssum, v1 = lg[i1] / ssum;
    float winv = 1.0f / (v0 + v1);
    g_te[2 * t] = i0; g_te[2 * t + 1] = i1;
    g_tw[2 * t] = v0 * winv; g_tw[2 * t + 1] = v1 * winv;
    atomicAdd(&g_counts[i0], 1);
    atomicAdd(&g_counts[i1], 1);
}

__global__ void scan_kernel() {
    int acc = 0;
    for (int e = 0; e < NE; e++) {
        g_offsets[e] = acc;
        acc += g_counts[e];
        g_cursor[e] = 0;
    }
}

__global__ void assign_kernel() {
    int t = blockIdx.x * blockDim.x + threadIdx.x;
    if (t >= TB) return;
    for (int kk = 0; kk < 2; kk++) {
        int e = g_te[2 * t + kk];
        int pos = g_offsets[e] + atomicAdd(&g_cursor[e], 1);
        g_rowtok[pos] = t;
        g_roww[pos] = g_tw[2 * t + kk];
        g_perm[2 * t + kk] = pos;
    }
}

// ---------------- host orchestration ----------------
extern "C" void kernel_launch(void* const* d_in, const int* in_sizes, int n_in,
                              void* d_out, int out_size) {
    (void)in_sizes; (void)n_in; (void)out_size;
    const int*   ids   = (const int*)  d_in[0];
    const float* emb   = (const float*)d_in[1];
    const float* ln1_g = (const float*)d_in[2];
    const float* ln1_b = (const float*)d_in[3];
    const float* ln2_g = (const float*)d_in[4];
    const float* ln2_b = (const float*)d_in[5];
    const float* Wq    = (const float*)d_in[6];
    const float* Wkv   = (const float*)d_in[7];
    const float* Wk    = (const float*)d_in[8];
    const float* Wv    = (const float*)d_in[9];
    const float* Wo    = (const float*)d_in[10];
    const float* Wg    = (const float*)d_in[11];
    const float* W1    = (const float*)d_in[12];
    const float* b1    = (const float*)d_in[13];
    const float* W2    = (const float*)d_in[14];
    const float* b2    = (const float*)d_in[15];
    const float* lnf_g = (const float*)d_in[16];
    const float* lnf_b = (const float*)d_in[17];
    const float* Wout  = (const float*)d_in[18];

    cudaFuncSetAttribute(qkv1_kernel,  cudaFuncAttributeMaxDynamicSharedMemorySize, GS16);
    cudaFuncSetAttribute(kv2_kernel,   cudaFuncAttributeMaxDynamicSharedMemorySize, GS16);
    cudaFuncSetAttribute(wo_kernel,    cudaFuncAttributeMaxDynamicSharedMemorySize, GS16);
    cudaFuncSetAttribute(moe1_kernel,  cudaFuncAttributeMaxDynamicSharedMemorySize, GS16);
    cudaFuncSetAttribute(moe2_kernel,  cudaFuncAttributeMaxDynamicSharedMemorySize, GS16);
    cudaFuncSetAttribute(lmhead_kernel, cudaFuncAttributeMaxDynamicSharedMemorySize, GS16);
    cudaFuncSetAttribute(attn_kernel,  cudaFuncAttributeMaxDynamicSharedMemorySize, ASMEM);

    __half *wqh, *wkvh, *wkh, *wvh, *woh, *w1h, *w2h, *wouth;
    cudaGetSymbolAddress((void**)&wqh,  g_wqh);
    cudaGetSymbolAddress((void**)&wkvh, g_wkvh);
    cudaGetSymbolAddress((void**)&wkh,  g_wkh);
    cudaGetSymbolAddress((void**)&wvh,  g_wvh);
    cudaGetSymbolAddress((void**)&woh,  g_woh);
    cudaGetSymbolAddress((void**)&w1h,  g_w1h);
    cudaGetSymbolAddress((void**)&w2h,  g_w2h);
    cudaGetSymbolAddress((void**)&wouth, g_wouth);

    auto wch = [&](const float* s, __half* h, size_t n) {
        int n4 = (int)(n / 4);
        wconvh_kernel<<<(n4 + 255) / 256, 256>>>(s, h, n4);
    };

    // Launch order: 1-based #4 = qkv1 so ncu captures a GEMM.
    embed_ln_kernel<<<TB, 256>>>(ids, emb, ln1_g, ln1_b);                     // 1
    wch(Wq, wqh, (size_t)NLAYER * DIM * DIM);                                 // 2
    {
        int n4 = NLAYER * DIM * DLAT / 4;                                     // 3
        wconvh3_kernel<<<dim3((n4 + 255) / 256, 3), 256>>>(
            Wkv, wkvh, Wk, wkh, Wv, wvh, n4);
    }

    for (int l = 0; l < NLAYER; l++) {
        // --- attention block ---
        qkv1_kernel<<<dim3(15, TB / 128), 256, GS16>>>(l);                    // 4 (l==0)
        kv2_kernel<<<dim3(24, TB / 128), 256, GS16>>>(l);
        rope_kernel<<<(TB * NH * 32 + 255) / 256, 256>>>();
        attn_kernel<<<dim3(SEQ / AQ, BATCH * NH), 256, ASMEM>>>();
        if (l == 0) {
            wch(Wo,   woh,  (size_t)NLAYER * DIM * DIM);
            wch(W1,   w1h,  (size_t)NLAYER * NE * DIM * DFF);
            wch(W2,   w2h,  (size_t)NLAYER * NE * DFF * DIM);
            wch(Wout, wouth, (size_t)DIM * NV);
        }
        wo_kernel<<<dim3(DIM / 64, TB / 128), 256, GS16>>>(l);

        // --- MoE block ---
        ln_kernel<<<TB, 256>>>(ln2_g + l * DIM, ln2_b + l * DIM);
        gate_kernel<<<TB, 256>>>(Wg + (size_t)l * DIM * NE);
        topk_kernel<<<TB / 256, 256>>>();
        scan_kernel<<<1, 1>>>();
        assign_kernel<<<TB / 256, 256>>>();
        moe1_kernel<<<dim3(DFF / 64, 2 * TB / 128, NE), 256, GS16>>>(b1, l);
        moe2_kernel<<<dim3(DIM / 64, 2 * TB / 128, NE), 256, GS16>>>(b2, l);

        // --- fused scatter + next LN (ln1 of next layer, or lnf) ---
        if (l + 1 < NLAYER)
            scatter_ln_kernel<<<TB, 256>>>(ln1_g + (l + 1) * DIM, ln1_b + (l + 1) * DIM);
        else
            scatter_ln_kernel<<<TB, 256>>>(lnf_g, lnf_b);
    }

    // --- LM head (fp16 2-pass) ---
    lmhead_kernel<<<dim3(NV / 64, TB / 128), 256, GS16>>>((float*)d_out);
}

// round 17
// speedup vs baseline: 1.6979x; 1.0006x over previous
#include <cuda_runtime.h>
#include <cuda_fp16.h>
#include <math.h>
#include <stdint.h>

// ---------------- problem dims ----------------
#define TB 2048
#define SEQ 1024
#define BATCH 2
#define DIM 768
#define NH 12
#define HD 64
#define DLAT 192
#define DFF 3072
#define NE 8
#define NV 32000
#define NLAYER 2

#define FLAG_ACC 1
#define FLAG_GELU 2

// ---------------- fp32 scratch ----------------
__device__ float g_x[TB * DIM];
__device__ float g_h[TB * DIM];
__device__ float g_q[TB * DIM];
__device__ float g_k[TB * DIM];
__device__ float g_v[TB * DIM];
__device__ float g_yff[2 * TB * DIM];
__device__ float g_logits[TB * NE];
__device__ float g_tw[TB * 2];
__device__ int   g_te[TB * 2];
__device__ int   g_counts[NE];
__device__ int   g_offsets[NE];
__device__ int   g_cursor[NE];
__device__ int   g_rowtok[2 * TB];
__device__ float g_roww[2 * TB];
__device__ int   g_perm[2 * TB];

// ---------------- fp16 hi/lo activations ----------------
__device__ __half g_hh[TB * DIM],  g_hl[TB * DIM];
__device__ __half g_lath[TB * DLAT], g_latl[TB * DLAT];
__device__ __half g_aoh[TB * DIM], g_aol[TB * DIM];
__device__ __half g_hffh[2 * TB * DFF], g_hffl[2 * TB * DFF];

// ---------------- fp16 weights (hi only; 2-pass scheme) ----------------
__device__ __half g_wqh[NLAYER * DIM * DIM];
__device__ __half g_wkvh[NLAYER * DIM * DLAT];
__device__ __half g_wkh[NLAYER * DLAT * DIM];
__device__ __half g_wvh[NLAYER * DLAT * DIM];
__device__ __half g_woh[NLAYER * DIM * DIM];
__device__ __half g_w1h[NLAYER * NE * DIM * DFF];
__device__ __half g_w2h[NLAYER * NE * DFF * DIM];
__device__ __half g_wouth[DIM * NV];

// ---------------- helpers ----------------
__device__ __forceinline__ uint32_t smem_u32(const void* p) {
    uint32_t a;
    asm("{ .reg .u64 t; cvta.to.shared.u64 t, %1; cvt.u32.u64 %0, t; }" : "=r"(a) : "l"(p));
    return a;
}
__device__ __forceinline__ float gelu_f(float x) {
    const float k0 = 0.7978845608028654f;
    float x3 = x * x * x;
    return 0.5f * x * (1.0f + tanhf(k0 * (x + 0.044715f * x3)));
}
__device__ __forceinline__ void mma16h(float d[4], const uint32_t a[4], const uint32_t b[2]) {
    asm volatile(
        "mma.sync.aligned.m16n8k16.row.col.f32.f16.f16.f32 "
        "{%0,%1,%2,%3},{%4,%5,%6,%7},{%8,%9},{%0,%1,%2,%3};"
        : "+f"(d[0]), "+f"(d[1]), "+f"(d[2]), "+f"(d[3])
        : "r"(a[0]), "r"(a[1]), "r"(a[2]), "r"(a[3]),
          "r"(b[0]), "r"(b[1]));
}
__device__ __forceinline__ void ldsm4(uint32_t r[4], uint32_t addr) {
    asm volatile("ldmatrix.sync.aligned.m8n8.x4.shared.b16 {%0,%1,%2,%3}, [%4];"
                 : "=r"(r[0]), "=r"(r[1]), "=r"(r[2]), "=r"(r[3]) : "r"(addr));
}
__device__ __forceinline__ void ldsm4t(uint32_t& r0, uint32_t& r1, uint32_t& r2,
                                       uint32_t& r3, uint32_t addr) {
    asm volatile("ldmatrix.sync.aligned.m8n8.x4.trans.shared.b16 {%0,%1,%2,%3}, [%4];"
                 : "=r"(r0), "=r"(r1), "=r"(r2), "=r"(r3) : "r"(addr));
}
__device__ __forceinline__ void cpa16(uint32_t dst, const void* src, int sz) {
    asm volatile("cp.async.cg.shared.global [%0], [%1], 16, %2;"
                 :: "r"(dst), "l"(src), "r"(sz) : "memory");
}
__device__ __forceinline__ void cpa16f(uint32_t dst, const void* src) {
    asm volatile("cp.async.cg.shared.global [%0], [%1], 16;"
                 :: "r"(dst), "l"(src) : "memory");
}
#define CP_COMMIT() asm volatile("cp.async.commit_group;" ::: "memory")
#define CP_WAIT1()  asm volatile("cp.async.wait_group 1;" ::: "memory")

// fp16 hi/lo store of a fp32 value
__device__ __forceinline__ void store_hf(__half* hp, __half* lp, size_t ix, float val) {
    __half hh = __float2half_rn(val);
    hp[ix] = hh;
    lp[ix] = __float2half_rn(val - __half2float(hh));
}

// ---------------- weight fp32 -> fp16 conversion ----------------
__device__ __forceinline__ void wconvh_body(const float* __restrict__ s,
                                            __half* __restrict__ h, int i, int n4) {
    if (i >= n4) return;
    float4 v = ((const float4*)s)[i];
    __half2 p0 = __floats2half2_rn(v.x, v.y);
    __half2 p1 = __floats2half2_rn(v.z, v.w);
    ((uint2*)h)[i] = make_uint2(*(uint32_t*)&p0, *(uint32_t*)&p1);
}
__global__ void wconvh_kernel(const float* __restrict__ s, __half* __restrict__ h, int n4) {
    wconvh_body(s, h, blockIdx.x * blockDim.x + threadIdx.x, n4);
}
__global__ void wconvh3_kernel(const float* __restrict__ s0, __half* __restrict__ h0,
                               const float* __restrict__ s1, __half* __restrict__ h1,
                               const float* __restrict__ s2, __half* __restrict__ h2,
                               int n4) {
    const float* s; __half* h;
    if (blockIdx.y == 0)      { s = s0; h = h0; }
    else if (blockIdx.y == 1) { s = s1; h = h1; }
    else                      { s = s2; h = h2; }
    wconvh_body(s, h, blockIdx.x * blockDim.x + threadIdx.x, n4);
}

// =====================================================================
//   fp16 2-pass mma.sync GEMM: D = (Ah + Al) @ B
//   M128 variant: 128x64 tile, 3 CTAs/SM (big-grid GEMMs).
// =====================================================================
#define A_ROW_B 80
#define B_ROW_B 144
#define H_AL_B 10240
#define H_B_B 20480
#define H_STAGE_B 25088
#define NSTAGE 3
#define GS16 (H_STAGE_B * NSTAGE)

__device__ __forceinline__ void gemm16_tile(
    const __half* __restrict__ Ah, const __half* __restrict__ Al,
    const int* __restrict__ Aidx,
    const __half* __restrict__ B, const float* __restrict__ bias,
    float* __restrict__ C, __half* __restrict__ Chi, __half* __restrict__ Clo,
    int Mv, int N, int K, int m0, int n0, int flags)
{
    extern __shared__ uint32_t smu[];
    const uint32_t sb0 = smem_u32(smu);
    int tid = threadIdx.x, lane = tid & 31, warp = tid >> 5;
    int wm = (warp >> 1) * 32, wn = (warp & 1) * 32;

    int jA = tid & 3, rA = tid >> 2;
    int kB = tid >> 3, jB = tid & 7;
    int gmr0 = m0 + rA, gmr1 = m0 + rA + 64;
    int szA0 = gmr0 < Mv ? 16 : 0;
    int szA1 = gmr1 < Mv ? 16 : 0;
    int row0 = gmr0 < Mv ? (Aidx ? Aidx[gmr0] : gmr0) : 0;
    int row1 = gmr1 < Mv ? (Aidx ? Aidx[gmr1] : gmr1) : 0;
    const __half* pAh0 = Ah + (size_t)row0 * K + jA * 8;
    const __half* pAl0 = Al + (size_t)row0 * K + jA * 8;
    const __half* pAh1 = Ah + (size_t)row1 * K + jA * 8;
    const __half* pAl1 = Al + (size_t)row1 * K + jA * 8;
    const __half* pB = B + (size_t)kB * N + n0 + jB * 8;
    uint32_t dA0 = rA * A_ROW_B + jA * 16;
    uint32_t dA1 = dA0 + 64 * A_ROW_B;
    uint32_t dB  = kB * B_ROW_B + jB * 16;

    const int nk = K / 32;

    auto load_stage = [&](int c) {
        if (c < nk) {
            uint32_t st = sb0 + (c % NSTAGE) * H_STAGE_B;
            int kc = c * 32;
            cpa16(st + dA0, pAh0 + kc, szA0);
            cpa16(st + dA1, pAh1 + kc, szA1);
            cpa16(st + H_AL_B + dA0, pAl0 + kc, szA0);
            cpa16(st + H_AL_B + dA1, pAl1 + kc, szA1);
            cpa16f(st + H_B_B + dB, pB + (size_t)kc * N);
        }
        CP_COMMIT();
    };

    float acc[2][4][4] = {};

    load_stage(0);
    load_stage(1);

    uint32_t aAddr = (uint32_t)((wm + (lane & 15)) * A_ROW_B + ((lane >> 4) << 4));
    uint32_t bAddr = (uint32_t)(H_B_B + (lane & 15) * B_ROW_B
                                + (wn + ((lane >> 4) << 3)) * 2);

    for (int c = 0; c < nk; c++) {
        CP_WAIT1();
        __syncthreads();
        load_stage(c + 2);

        uint32_t st = sb0 + (c % NSTAGE) * H_STAGE_B;
#pragma unroll
        for (int ss = 0; ss < 2; ss++) {
            uint32_t ah[2][4], al[2][4], bh[4][2];
#pragma unroll
            for (int mt = 0; mt < 2; mt++) {
                uint32_t ao = st + aAddr + mt * 16 * A_ROW_B + ss * 32;
                ldsm4(ah[mt], ao);
                ldsm4(al[mt], ao + H_AL_B);
            }
#pragma unroll
            for (int ntp = 0; ntp < 2; ntp++) {
                uint32_t bo = st + bAddr + ss * 16 * B_ROW_B + ntp * 32;
                ldsm4t(bh[2 * ntp][0], bh[2 * ntp][1],
                       bh[2 * ntp + 1][0], bh[2 * ntp + 1][1], bo);
            }
#pragma unroll
            for (int mt = 0; mt < 2; mt++)
#pragma unroll
                for (int nt = 0; nt < 4; nt++) mma16h(acc[mt][nt], ah[mt], bh[nt]);
#pragma unroll
            for (int mt = 0; mt < 2; mt++)
#pragma unroll
                for (int nt = 0; nt < 4; nt++) mma16h(acc[mt][nt], al[mt], bh[nt]);
        }
    }

    int row = lane >> 2, cc = lane & 3;
#pragma unroll
    for (int mt = 0; mt < 2; mt++) {
#pragma unroll
        for (int h = 0; h < 2; h++) {
            int r = m0 + wm + mt * 16 + row + h * 8;
            if (r >= Mv) continue;
#pragma unroll
            for (int nt = 0; nt < 4; nt++) {
#pragma unroll
                for (int j = 0; j < 2; j++) {
                    int cn = n0 + wn + nt * 8 + cc * 2 + j;
                    float val = acc[mt][nt][h * 2 + j];
                    if (bias) val += bias[cn];
                    if (flags & FLAG_GELU) val = gelu_f(val);
                    size_t ix = (size_t)r * N + cn;
                    if (flags & FLAG_ACC) C[ix] += val;
                    else if (C) C[ix] = val;
                    if (Chi) store_hf(Chi, Clo, ix, val);
                }
            }
        }
    }
}

// =====================================================================
//   M64 variant: 64x64 tile, 8 warps (2m x 4n), warp tile 32x16.
//   Stage: Ah 5120B | Al 5120B | B 4608B -> 14848B; 3 stages = 44.5KB.
//   4 CTAs/SM for the grid-starved projection GEMMs.
// =====================================================================
#define H64_AL_B 5120
#define H64_B_B 10240
#define H64_STAGE_B 14848
#define GS64 (H64_STAGE_B * NSTAGE)

__device__ __forceinline__ void gemm16_tile64(
    const __half* __restrict__ Ah, const __half* __restrict__ Al,
    const __half* __restrict__ B,
    float* __restrict__ C, __half* __restrict__ Chi, __half* __restrict__ Clo,
    int N, int K, int m0, int n0, int flags)
{
    extern __shared__ uint32_t smu[];
    const uint32_t sb0 = smem_u32(smu);
    int tid = threadIdx.x, lane = tid & 31, warp = tid >> 5;
    int wm = (warp >> 2) * 32, wn = (warp & 3) * 16;

    int jA = tid & 3, rA = tid >> 2;          // 64 rows x 4 chunks
    int kB = tid >> 3, jB = tid & 7;
    const __half* pAh0 = Ah + (size_t)(m0 + rA) * K + jA * 8;
    const __half* pAl0 = Al + (size_t)(m0 + rA) * K + jA * 8;
    const __half* pB = B + (size_t)kB * N + n0 + jB * 8;
    uint32_t dA0 = rA * A_ROW_B + jA * 16;
    uint32_t dB  = kB * B_ROW_B + jB * 16;

    const int nk = K / 32;

    auto load_stage = [&](int c) {
        if (c < nk) {
            uint32_t st = sb0 + (c % NSTAGE) * H64_STAGE_B;
            int kc = c * 32;
            cpa16f(st + dA0, pAh0 + kc);
            cpa16f(st + H64_AL_B + dA0, pAl0 + kc);
            cpa16f(st + H64_B_B + dB, pB + (size_t)kc * N);
        }
        CP_COMMIT();
    };

    float acc[2][2][4] = {};

    load_stage(0);
    load_stage(1);

    uint32_t aAddr = (uint32_t)((wm + (lane & 15)) * A_ROW_B + ((lane >> 4) << 4));
    uint32_t bAddr = (uint32_t)(H64_B_B + (lane & 15) * B_ROW_B
                                + (wn + ((lane >> 4) << 3)) * 2);

    for (int c = 0; c < nk; c++) {
        CP_WAIT1();
        __syncthreads();
        load_stage(c + 2);

        uint32_t st = sb0 + (c % NSTAGE) * H64_STAGE_B;
#pragma unroll
        for (int ss = 0; ss < 2; ss++) {
            uint32_t ah[2][4], al[2][4], bh[2][2];
#pragma unroll
            for (int mt = 0; mt < 2; mt++) {
                uint32_t ao = st + aAddr + mt * 16 * A_ROW_B + ss * 32;
                ldsm4(ah[mt], ao);
                ldsm4(al[mt], ao + H64_AL_B);
            }
            {
                uint32_t bo = st + bAddr + ss * 16 * B_ROW_B;
                ldsm4t(bh[0][0], bh[0][1], bh[1][0], bh[1][1], bo);
            }
#pragma unroll
            for (int mt = 0; mt < 2; mt++)
#pragma unroll
                for (int nt = 0; nt < 2; nt++) mma16h(acc[mt][nt], ah[mt], bh[nt]);
#pragma unroll
            for (int mt = 0; mt < 2; mt++)
#pragma unroll
                for (int nt = 0; nt < 2; nt++) mma16h(acc[mt][nt], al[mt], bh[nt]);
        }
    }

    int row = lane >> 2, cc = lane & 3;
#pragma unroll
    for (int mt = 0; mt < 2; mt++) {
#pragma unroll
        for (int h = 0; h < 2; h++) {
            int r = m0 + wm + mt * 16 + row + h * 8;
#pragma unroll
            for (int nt = 0; nt < 2; nt++) {
#pragma unroll
                for (int j = 0; j < 2; j++) {
                    int cn = n0 + wn + nt * 8 + cc * 2 + j;
                    float val = acc[mt][nt][h * 2 + j];
                    size_t ix = (size_t)r * N + cn;
                    if (flags & FLAG_ACC) C[ix] += val;
                    else if (C) C[ix] = val;
                    if (Chi) store_hf(Chi, Clo, ix, val);
                }
            }
        }
    }
}

// ---------------- GEMM kernels ----------------
__global__ void __launch_bounds__(256, 4) qkv1_kernel(int l) {
    int bx = blockIdx.x;
    size_t wq = (size_t)l * DIM * DIM, wkv = (size_t)l * DIM * DLAT;
    if (bx < 12)
        gemm16_tile64(g_hh, g_hl, g_wqh + wq,
                      g_q, nullptr, nullptr, DIM, DIM, blockIdx.y * 64, bx * 64, 0);
    else
        gemm16_tile64(g_hh, g_hl, g_wkvh + wkv,
                      nullptr, g_lath, g_latl, DLAT, DIM,
                      blockIdx.y * 64, (bx - 12) * 64, 0);
}

__global__ void __launch_bounds__(256, 4) kv2_kernel(int l) {
    int bx = blockIdx.x;
    size_t w = (size_t)l * DLAT * DIM;
    if (bx < 12)
        gemm16_tile64(g_lath, g_latl, g_wkh + w,
                      g_k, nullptr, nullptr, DIM, DLAT, blockIdx.y * 64, bx * 64, 0);
    else
        gemm16_tile64(g_lath, g_latl, g_wvh + w,
                      g_v, nullptr, nullptr, DIM, DLAT,
                      blockIdx.y * 64, (bx - 12) * 64, 0);
}

__global__ void __launch_bounds__(256, 4) wo_kernel(int l) {
    size_t w = (size_t)l * DIM * DIM;
    gemm16_tile64(g_aoh, g_aol, g_woh + w,
                  g_x, nullptr, nullptr, DIM, DIM,
                  blockIdx.y * 64, blockIdx.x * 64, FLAG_ACC);
}

__global__ void __launch_bounds__(256, 3) moe1_kernel(const float* __restrict__ b1, int l) {
    int e = blockIdx.z;
    int cnt = g_counts[e];
    int m0 = blockIdx.y * 128;
    if (m0 >= cnt) return;
    int off = g_offsets[e];
    size_t w = ((size_t)l * NE + e) * DIM * DFF;
    gemm16_tile(g_hh, g_hl, g_rowtok + off, g_w1h + w,
                b1 + ((size_t)l * NE + e) * DFF,
                nullptr, g_hffh + (size_t)off * DFF, g_hffl + (size_t)off * DFF,
                cnt, DFF, DIM, m0, blockIdx.x * 64, FLAG_GELU);
}

__global__ void __launch_bounds__(256, 3) moe2_kernel(const float* __restrict__ b2, int l) {
    int e = blockIdx.z;
    int cnt = g_counts[e];
    int m0 = blockIdx.y * 128;
    if (m0 >= cnt) return;
    int off = g_offsets[e];
    size_t w = ((size_t)l * NE + e) * DFF * DIM;
    gemm16_tile(g_hffh + (size_t)off * DFF, g_hffl + (size_t)off * DFF, nullptr,
                g_w2h + w, b2 + ((size_t)l * NE + e) * DIM,
                g_yff + (size_t)off * DIM, nullptr, nullptr,
                cnt, DIM, DFF, m0, blockIdx.x * 64, 0);
}

__global__ void __launch_bounds__(256, 3) lmhead_kernel(float* __restrict__ out) {
    gemm16_tile(g_hh, g_hl, nullptr, g_wouth, nullptr,
                out, nullptr, nullptr, TB, NV, DIM,
                blockIdx.y * 128, blockIdx.x * 64, 0);
}

// ---------------- fused embed + ln1(layer0) ----------------
__global__ void embed_ln_kernel(const int* __restrict__ ids, const float* __restrict__ emb,
                                const float* __restrict__ g, const float* __restrict__ b) {
    int row = blockIdx.x;
    int t = threadIdx.x;
    const float* src = emb + (size_t)ids[row] * DIM;
    float v0 = src[t], v1 = src[t + 256], v2 = src[t + 512];
    size_t base = (size_t)row * DIM;
    g_x[base + t] = v0; g_x[base + t + 256] = v1; g_x[base + t + 512] = v2;
    __shared__ float red[256];
    red[t] = v0 + v1 + v2;
    __syncthreads();
    for (int o = 128; o > 0; o >>= 1) { if (t < o) red[t] += red[t + o]; __syncthreads(); }
    float mean = red[0] * (1.0f / DIM);
    __syncthreads();
    float d0 = v0 - mean, d1 = v1 - mean, d2 = v2 - mean;
    red[t] = d0 * d0 + d1 * d1 + d2 * d2;
    __syncthreads();
    for (int o = 128; o > 0; o >>= 1) { if (t < o) red[t] += red[t + o]; __syncthreads(); }
    float rstd = rsqrtf(red[0] * (1.0f / DIM) + 1e-6f);
#pragma unroll
    for (int i = 0; i < 3; i++) {
        int d = t + i * 256;
        float dv = (i == 0 ? d0 : (i == 1 ? d1 : d2));
        float val = dv * rstd * g[d] + b[d];
        g_h[base + d] = val;
        store_hf(g_hh, g_hl, base + d, val);
    }
}

// ---------------- layernorm over g_x (ln2 after wo) ----------------
__global__ void ln_kernel(const float* __restrict__ g, const float* __restrict__ b) {
    int row = blockIdx.x;
    int t = threadIdx.x;
    const float* xr = g_x + (size_t)row * DIM;
    float v0 = xr[t], v1 = xr[t + 256], v2 = xr[t + 512];
    __shared__ float red[256];
    red[t] = v0 + v1 + v2;
    __syncthreads();
    for (int o = 128; o > 0; o >>= 1) { if (t < o) red[t] += red[t + o]; __syncthreads(); }
    float mean = red[0] * (1.0f / DIM);
    __syncthreads();
    float d0 = v0 - mean, d1 = v1 - mean, d2 = v2 - mean;
    red[t] = d0 * d0 + d1 * d1 + d2 * d2;
    __syncthreads();
    for (int o = 128; o > 0; o >>= 1) { if (t < o) red[t] += red[t + o]; __syncthreads(); }
    float rstd = rsqrtf(red[0] * (1.0f / DIM) + 1e-6f);
    size_t base = (size_t)row * DIM;
#pragma unroll
    for (int i = 0; i < 3; i++) {
        int d = t + i * 256;
        float dv = (i == 0 ? d0 : (i == 1 ? d1 : d2));
        float val = dv * rstd * g[d] + b[d];
        g_h[base + d] = val;
        store_hf(g_hh, g_hl, base + d, val);
    }
}

// ---------------- fused MoE scatter + next layernorm ----------------
__global__ void scatter_ln_kernel(const float* __restrict__ g, const float* __restrict__ b) {
    int row = blockIdx.x;
    int t = threadIdx.x;
    int r0 = g_perm[2 * row], r1 = g_perm[2 * row + 1];
    float w0 = g_roww[r0], w1 = g_roww[r1];
    size_t base = (size_t)row * DIM;
    const float* y0 = g_yff + (size_t)r0 * DIM;
    const float* y1 = g_yff + (size_t)r1 * DIM;
    float v[3];
#pragma unroll
    for (int i = 0; i < 3; i++) {
        int d = t + i * 256;
        v[i] = g_x[base + d] + w0 * y0[d] + w1 * y1[d];
        g_x[base + d] = v[i];
    }
    __shared__ float red[256];
    red[t] = v[0] + v[1] + v[2];
    __syncthreads();
    for (int o = 128; o > 0; o >>= 1) { if (t < o) red[t] += red[t + o]; __syncthreads(); }
    float mean = red[0] * (1.0f / DIM);
    __syncthreads();
    float d0 = v[0] - mean, d1 = v[1] - mean, d2 = v[2] - mean;
    red[t] = d0 * d0 + d1 * d1 + d2 * d2;
    __syncthreads();
    for (int o = 128; o > 0; o >>= 1) { if (t < o) red[t] += red[t + o]; __syncthreads(); }
    float rstd = rsqrtf(red[0] * (1.0f / DIM) + 1e-6f);
#pragma unroll
    for (int i = 0; i < 3; i++) {
        int d = t + i * 256;
        float dv = (i == 0 ? d0 : (i == 1 ? d1 : d2));
        float val = dv * rstd * g[d] + b[d];
        g_h[base + d] = val;
        store_hf(g_hh, g_hl, base + d, val);
    }
}

// ---------------- RoPE on q and k (in place) ----------------
__global__ void rope_kernel() {
    int idx = blockIdx.x * blockDim.x + threadIdx.x;
    if (idx >= TB * NH * 32) return;
    int j = idx & 31;
    int h = (idx >> 5) % NH;
    int t = idx / (32 * NH);
    int s = t % SEQ;
    float inv = exp2f(-(float)j * 0.41524101186092029f);
    float ang = (float)s * inv;
    float sn, cs;
    sincosf(ang, &sn, &cs);
    int base = t * DIM + h * HD;
    float a = g_q[base + j], b2 = g_q[base + 32 + j];
    g_q[base + j]      = a * cs - b2 * sn;
    g_q[base + 32 + j] = b2 * cs + a * sn;
    a = g_k[base + j]; b2 = g_k[base + 32 + j];
    g_k[base + j]      = a * cs - b2 * sn;
    g_k[base + 32 + j] = b2 * cs + a * sn;
}

// =====================================================================
//  flash attention (fp32, smem-tiled); output fp16 hi/lo for Wo GEMM
//  3 CTAs/SM (smem 50.7KB x3 = 152KB; grid 384 fully resident).
// =====================================================================
#define AQ 64
#define AKT 32
#define KVS 68
#define AQS_F (AQ * HD)
#define KVBUF_F (AKT * KVS)
#define KVSTG_F (2 * KVBUF_F)
#define ASMEM ((AQS_F + 2 * KVSTG_F) * 4)

__global__ void __launch_bounds__(256, 3) attn_kernel() {
    extern __shared__ float sm[];
    float* Qs = sm;
    float* KV = sm + AQS_F;
    const uint32_t kvu = smem_u32(KV);

    int tid = threadIdx.x, lane = tid & 31, w = tid >> 5;
    int qb = 15 - blockIdx.x;
    int bh = blockIdx.y;
    int b = bh / NH, h = bh % NH;
    int q0 = qb * AQ;
    size_t kvbase = ((size_t)b * SEQ) * DIM + h * HD;

    {
        const float* qsrc = g_q + ((size_t)(b * SEQ + q0)) * DIM + h * HD;
#pragma unroll
        for (int i = 0; i < 4; i++) {
            int e4 = tid + i * 256;
            int r = e4 >> 4, dq = (e4 & 15) * 4;
            float4 v = *(const float4*)(qsrc + (size_t)r * DIM + dq);
            v.x *= 0.125f; v.y *= 0.125f; v.z *= 0.125f; v.w *= 0.125f;
            *(float4*)(Qs + r * HD + dq) = v;
        }
    }

    const int nt = 2 * qb + 2;

    auto load_tile = [&](int t) {
        uint32_t dstb = kvu + (t & 1) * (KVSTG_F * 4);
#pragma unroll
        for (int i = 0; i < 2; i++) {
            int c = tid + i * 256;
            int r = c >> 4, of = (c & 15) * 4;
            size_t src = kvbase + (size_t)(t * AKT + r) * DIM + of;
            uint32_t d = dstb + (r * KVS + of) * 4;
            cpa16f(d, g_k + src);
            cpa16f(d + KVBUF_F * 4, g_v + src);
        }
        CP_COMMIT();
    };

    float m[8], l[8], a0[8], a1[8], sc[8];
#pragma unroll
    for (int q = 0; q < 8; q++) { m[q] = -1e30f; l[q] = 0.f; a0[q] = 0.f; a1[q] = 0.f; }

    const float* qsw = Qs + (w * 8) * HD;
    int qg0 = q0 + w * 8;

    load_tile(0);

    for (int t = 0; t < nt; t++) {
        if (t + 1 < nt) load_tile(t + 1); else CP_COMMIT();
        CP_WAIT1();
        __syncthreads();

        const float* Ksb = KV + (t & 1) * KVSTG_F;
        const float* Vsb = Ksb + KVBUF_F;

#pragma unroll
        for (int q = 0; q < 8; q++) sc[q] = 0.f;
#pragma unroll
        for (int dq = 0; dq < 16; dq++) {
            float4 kv = *(const float4*)(Ksb + lane * KVS + dq * 4);
#pragma unroll
            for (int q = 0; q < 8; q++) {
                float4 qv = *(const float4*)(qsw + q * HD + dq * 4);
                sc[q] += qv.x * kv.x + qv.y * kv.y + qv.z * kv.z + qv.w * kv.w;
            }
        }
        if (t >= nt - 2) {
            int kg = t * AKT + lane;
#pragma unroll
            for (int q = 0; q < 8; q++)
                if (kg > qg0 + q) sc[q] = -1e30f;
        }

#pragma unroll
        for (int q = 0; q < 8; q++) {
            float tm = sc[q];
#pragma unroll
            for (int o = 16; o; o >>= 1) tm = fmaxf(tm, __shfl_xor_sync(0xffffffffu, tm, o));
            float mn = fmaxf(m[q], tm);
            float corr = __expf(m[q] - mn);
            float p = __expf(sc[q] - mn);
            float ps = p;
#pragma unroll
            for (int o = 16; o; o >>= 1) ps += __shfl_xor_sync(0xffffffffu, ps, o);
            l[q] = l[q] * corr + ps;
            m[q] = mn;
            a0[q] *= corr;
            a1[q] *= corr;
            sc[q] = p;
        }

#pragma unroll
        for (int kk = 0; kk < AKT; kk++) {
            float v0 = Vsb[kk * KVS + lane];
            float v1 = Vsb[kk * KVS + lane + 32];
#pragma unroll
            for (int q = 0; q < 8; q++) {
                float pq = __shfl_sync(0xffffffffu, sc[q], kk);
                a0[q] += pq * v0;
                a1[q] += pq * v1;
            }
        }
        __syncthreads();
    }

#pragma unroll
    for (int q = 0; q < 8; q++) {
        float inv = 1.0f / l[q];
        float o0 = a0[q] * inv, o1 = a1[q] * inv;
        size_t ob = ((size_t)(b * SEQ + qg0 + q)) * DIM + h * HD;
        store_hf(g_aoh, g_aol, ob + lane, o0);
        store_hf(g_aoh, g_aol, ob + lane + 32, o1);
    }
}

// ---------------- MoE gate logits (also zeroes counts) ------------------
__global__ void gate_kernel(const float* __restrict__ Wg) {
    int tok = blockIdx.x;
    int e = threadIdx.x >> 5;
    int lane = threadIdx.x & 31;
    if (tok == 0 && threadIdx.x < NE) g_counts[threadIdx.x] = 0;
    const float* hr = g_h + (size_t)tok * DIM;
    float s = 0.f;
    for (int d = lane; d < DIM; d += 32) s += hr[d] * Wg[d * NE + e];
#pragma unroll
    for (int o = 16; o; o >>= 1) s += __shfl_xor_sync(0xffffffffu, s, o);
    if (lane == 0) g_logits[tok * NE + e] = s;
}

__global__ void topk_kernel() {
    int t = blockIdx.x * blockDim.x + threadIdx.x;
    if (t >= TB) return;
    float lg[NE];
    float m = -1e30f;
#pragma unroll
    for (int e = 0; e < NE; e++) { lg[e] = g_logits[t * NE + e]; m = fmaxf(m, lg[e]); }
    float ssum = 0.f;
#pragma unroll
    for (int e = 0; e < NE; e++) { lg[e] = expf(lg[e] - m); ssum += lg[e]; }
    int i0 = 0;
#pragma unroll
    for (int e = 1; e < NE; e++) if (lg[e] > lg[i0]) i0 = e;
    int i1 = (i0 == 0) ? 1 : 0;
#pragma unroll
    for (int e = 0; e < NE; e++) if (e != i0 && e != i1 && lg[e] > lg[i1]) i1 = e;
    float v0 = lg[i0] / ssum, v1 = lg[i1] / ssum;
    float winv = 1.0f / (v0 + v1);
    g_te[2 * t] = i0; g_te[2 * t + 1] = i1;
    g_tw[2 * t] = v0 * winv; g_tw[2 * t + 1] = v1 * winv;
    atomicAdd(&g_counts[i0], 1);
    atomicAdd(&g_counts[i1], 1);
}

__global__ void scan_kernel() {
    int acc = 0;
    for (int e = 0; e < NE; e++) {
        g_offsets[e] = acc;
        acc += g_counts[e];
        g_cursor[e] = 0;
    }
}

__global__ void assign_kernel() {
    int t = blockIdx.x * blockDim.x + threadIdx.x;
    if (t >= TB) return;
    for (int kk = 0; kk < 2; kk++) {
        int e = g_te[2 * t + kk];
        int pos = g_offsets[e] + atomicAdd(&g_cursor[e], 1);
        g_rowtok[pos] = t;
        g_roww[pos] = g_tw[2 * t + kk];
        g_perm[2 * t + kk] = pos;
    }
}

// ---------------- host orchestration ----------------
extern "C" void kernel_launch(void* const* d_in, const int* in_sizes, int n_in,
                              void* d_out, int out_size) {
    (void)in_sizes; (void)n_in; (void)out_size;
    const int*   ids   = (const int*)  d_in[0];
    const float* emb   = (const float*)d_in[1];
    const float* ln1_g = (const float*)d_in[2];
    const float* ln1_b = (const float*)d_in[3];
    const float* ln2_g = (const float*)d_in[4];
    const float* ln2_b = (const float*)d_in[5];
    const float* Wq    = (const float*)d_in[6];
    const float* Wkv   = (const float*)d_in[7];
    const float* Wk    = (const float*)d_in[8];
    const float* Wv    = (const float*)d_in[9];
    const float* Wo    = (const float*)d_in[10];
    const float* Wg    = (const float*)d_in[11];
    const float* W1    = (const float*)d_in[12];
    const float* b1    = (const float*)d_in[13];
    const float* W2    = (const float*)d_in[14];
    const float* b2    = (const float*)d_in[15];
    const float* lnf_g = (const float*)d_in[16];
    const float* lnf_b = (const float*)d_in[17];
    const float* Wout  = (const float*)d_in[18];

    cudaFuncSetAttribute(qkv1_kernel,  cudaFuncAttributeMaxDynamicSharedMemorySize, GS64);
    cudaFuncSetAttribute(kv2_kernel,   cudaFuncAttributeMaxDynamicSharedMemorySize, GS64);
    cudaFuncSetAttribute(wo_kernel,    cudaFuncAttributeMaxDynamicSharedMemorySize, GS64);
    cudaFuncSetAttribute(moe1_kernel,  cudaFuncAttributeMaxDynamicSharedMemorySize, GS16);
    cudaFuncSetAttribute(moe2_kernel,  cudaFuncAttributeMaxDynamicSharedMemorySize, GS16);
    cudaFuncSetAttribute(lmhead_kernel, cudaFuncAttributeMaxDynamicSharedMemorySize, GS16);
    cudaFuncSetAttribute(attn_kernel,  cudaFuncAttributeMaxDynamicSharedMemorySize, ASMEM);

    __half *wqh, *wkvh, *wkh, *wvh, *woh, *w1h, *w2h, *wouth;
    cudaGetSymbolAddress((void**)&wqh,  g_wqh);
    cudaGetSymbolAddress((void**)&wkvh, g_wkvh);
    cudaGetSymbolAddress((void**)&wkh,  g_wkh);
    cudaGetSymbolAddress((void**)&wvh,  g_wvh);
    cudaGetSymbolAddress((void**)&woh,  g_woh);
    cudaGetSymbolAddress((void**)&w1h,  g_w1h);
    cudaGetSymbolAddress((void**)&w2h,  g_w2h);
    cudaGetSymbolAddress((void**)&wouth, g_wouth);

    auto wch = [&](const float* s, __half* h, size_t n) {
        int n4 = (int)(n / 4);
        wconvh_kernel<<<(n4 + 255) / 256, 256>>>(s, h, n4);
    };

    // Launch order: 1-based #4 = qkv1 so ncu captures a GEMM.
    embed_ln_kernel<<<TB, 256>>>(ids, emb, ln1_g, ln1_b);                     // 1
    wch(Wq, wqh, (size_t)NLAYER * DIM * DIM);                                 // 2
    {
        int n4 = NLAYER * DIM * DLAT / 4;                                     // 3
        wconvh3_kernel<<<dim3((n4 + 255) / 256, 3), 256>>>(
            Wkv, wkvh, Wk, wkh, Wv, wvh, n4);
    }

    for (int l = 0; l < NLAYER; l++) {
        // --- attention block ---
        qkv1_kernel<<<dim3(15, TB / 64), 256, GS64>>>(l);                     // 4 (l==0)
        kv2_kernel<<<dim3(24, TB / 64), 256, GS64>>>(l);
        rope_kernel<<<(TB * NH * 32 + 255) / 256, 256>>>();
        attn_kernel<<<dim3(SEQ / AQ, BATCH * NH), 256, ASMEM>>>();
        if (l == 0) {
            wch(Wo,   woh,  (size_t)NLAYER * DIM * DIM);
            wch(W1,   w1h,  (size_t)NLAYER * NE * DIM * DFF);
            wch(W2,   w2h,  (size_t)NLAYER * NE * DFF * DIM);
            wch(Wout, wouth, (size_t)DIM * NV);
        }
        wo_kernel<<<dim3(DIM / 64, TB / 64), 256, GS64>>>(l);

        // --- MoE block ---
        ln_kernel<<<TB, 256>>>(ln2_g + l * DIM, ln2_b + l * DIM);
        gate_kernel<<<TB, 256>>>(Wg + (size_t)l * DIM * NE);
        topk_kernel<<<TB / 256, 256>>>();
        scan_kernel<<<1, 1>>>();
        assign_kernel<<<TB / 256, 256>>>();
        moe1_kernel<<<dim3(DFF / 64, 2 * TB / 128, NE), 256, GS16>>>(b1, l);
        moe2_kernel<<<dim3(DIM / 64, 2 * TB / 128, NE), 256, GS16>>>(b2, l);

        // --- fused scatter + next LN (ln1 of next layer, or lnf) ---
        if (l + 1 < NLAYER)
            scatter_ln_kernel<<<TB, 256>>>(ln1_g + (l + 1) * DIM, ln1_b + (l + 1) * DIM);
        else
            scatter_ln_kernel<<<TB, 256>>>(lnf_g, lnf_b);
    }

    // --- LM head (fp16 2-pass) ---
    lmhead_kernel<<<dim3(NV / 64, TB / 128), 256, GS16>>>((float*)d_out);
}